// round 9
// baseline (speedup 1.0000x reference)
#include <cuda_runtime.h>
#include <math.h>

#define Bn   16
#define CIN  512
#define Lr   1024
#define COUT 1024
#define KW   5
#define DW   512
#define HW   196
#define HALF 512

typedef unsigned uint_t;

// ---- scratch (device globals; no allocation allowed) ----
__device__ float g_wn[COUT * CIN * KW];        // normalized conv weights
__device__ float g_y[(size_t)Bn * COUT * Lr];  // conv output (pre-GLU)
__device__ float g_h[(size_t)Bn * HALF * Lr];  // GLU output / identity_attn
__device__ float g_q[(size_t)Bn * Lr * DW];    // fc1 output + word_embed
__device__ float g_score[(size_t)Bn * Lr * HW];
__device__ float g_ctx[(size_t)Bn * Lr * DW];

// ---- bf16x3 split helpers ----
__device__ __forceinline__ void split2(float v0, float v1, uint_t& hi, uint_t& lo) {
    asm("cvt.rn.bf16x2.f32 %0, %1, %2;" : "=r"(hi) : "f"(v1), "f"(v0));
    float h0 = __uint_as_float(hi << 16);
    float h1 = __uint_as_float(hi & 0xffff0000u);
    asm("cvt.rn.bf16x2.f32 %0, %1, %2;" : "=r"(lo) : "f"(v1 - h1), "f"(v0 - h0));
}

__device__ __forceinline__ void mma_bf16(float* c, const uint_t* a, const uint_t* b) {
    asm volatile(
        "mma.sync.aligned.m16n8k16.row.col.f32.bf16.bf16.f32 "
        "{%0,%1,%2,%3}, {%4,%5,%6,%7}, {%8,%9}, {%0,%1,%2,%3};"
        : "+f"(c[0]), "+f"(c[1]), "+f"(c[2]), "+f"(c[3])
        : "r"(a[0]), "r"(a[1]), "r"(a[2]), "r"(a[3]), "r"(b[0]), "r"(b[1]));
}

__device__ __forceinline__ void ldsm4(uint_t& r0, uint_t& r1, uint_t& r2, uint_t& r3,
                                      const uint_t* p) {
    uint_t a = (uint_t)__cvta_generic_to_shared(p);
    asm volatile("ldmatrix.sync.aligned.m8n8.x4.shared.b16 {%0,%1,%2,%3}, [%4];"
                 : "=r"(r0), "=r"(r1), "=r"(r2), "=r"(r3) : "r"(a));
}

#define PAD 12  // row stride words: {12r mod 32} covers all banks -> LDSM conflict-free

// One 16-wide k-chunk: warp computes 64x32 via 4x4 m16n8k16 tiles, 3-term bf16 split.
// Fragment loads via ldmatrix.x4 (12 per warp).
__device__ __forceinline__ void mma_chunk(const uint_t (*Ah)[PAD], const uint_t (*Al)[PAD],
                                          const uint_t (*Bh)[PAD], const uint_t (*Bl)[PAD],
                                          int wm, int wn, int lane, float acc[4][4][4]) {
    int l7 = lane & 7;
    int arow = ((lane >> 3) & 1) * 8 + l7;  // A x4 tile order: (r,k0-3),(r+8,k0-3),(r,k4-7),(r+8,k4-7)
    int acol = (lane >> 4) * 4;
    int brow = (lane >> 4) * 8 + l7;        // B x4 tile order: (n,k0-3),(n,k4-7),(n+8,k0-3),(n+8,k4-7)
    int bcol = ((lane >> 3) & 1) * 4;

    uint_t ah[4][4], al[4][4], bh[4][2], bl[4][2];
#pragma unroll
    for (int i = 0; i < 4; ++i) {
        int r0 = wm + i * 16;
        ldsm4(ah[i][0], ah[i][1], ah[i][2], ah[i][3], &Ah[r0 + arow][acol]);
        ldsm4(al[i][0], al[i][1], al[i][2], al[i][3], &Al[r0 + arow][acol]);
    }
#pragma unroll
    for (int jp = 0; jp < 2; ++jp) {
        int n0 = wn + jp * 16;
        ldsm4(bh[2 * jp][0], bh[2 * jp][1], bh[2 * jp + 1][0], bh[2 * jp + 1][1],
              &Bh[n0 + brow][bcol]);
        ldsm4(bl[2 * jp][0], bl[2 * jp][1], bl[2 * jp + 1][0], bl[2 * jp + 1][1],
              &Bl[n0 + brow][bcol]);
    }
#pragma unroll
    for (int i = 0; i < 4; ++i)
#pragma unroll
        for (int j = 0; j < 4; ++j) {
            mma_bf16(acc[i][j], ah[i], bh[j]);
            mma_bf16(acc[i][j], ah[i], bl[j]);
            mma_bf16(acc[i][j], al[i], bh[j]);
        }
}

#define ACC_INIT()                                    \
    float acc[4][4][4];                               \
    _Pragma("unroll") for (int i = 0; i < 4; ++i)     \
        _Pragma("unroll") for (int j = 0; j < 4; ++j) \
            _Pragma("unroll") for (int t = 0; t < 4; ++t) acc[i][j][t] = 0.f;

#define SMEM_DECL()                                     \
    __shared__ uint_t Ah[2][128][PAD], Al[2][128][PAD]; \
    __shared__ uint_t Bh[2][128][PAD], Bl[2][128][PAD];

// Staging index: thread owns (crow, ckp0..ckp0+3): 4 consecutive k-words -> STS.128.
#define STAGE_IDX() int crow = tid >> 1, ckp0 = (tid & 1) * 4;

#define COMMIT(buf)                                   \
    {                                                 \
        uint4 vh, vl;                                 \
        split2(sa[0].x, sa[0].y, vh.x, vl.x);         \
        split2(sa[1].x, sa[1].y, vh.y, vl.y);         \
        split2(sa[2].x, sa[2].y, vh.z, vl.z);         \
        split2(sa[3].x, sa[3].y, vh.w, vl.w);         \
        *(uint4*)&Ah[buf][crow][ckp0] = vh;           \
        *(uint4*)&Al[buf][crow][ckp0] = vl;           \
        split2(sb[0].x, sb[0].y, vh.x, vl.x);         \
        split2(sb[1].x, sb[1].y, vh.y, vl.y);         \
        split2(sb[2].x, sb[2].y, vh.z, vl.z);         \
        split2(sb[3].x, sb[3].y, vh.w, vl.w);         \
        *(uint4*)&Bh[buf][crow][ckp0] = vh;           \
        *(uint4*)&Bl[buf][crow][ckp0] = vl;           \
    }

// ================= weight norm =================
__global__ void wnorm_kernel(const float* __restrict__ v, const float* __restrict__ g) {
    int co = blockIdx.x;
    const float* vp = v + (size_t)co * (CIN * KW);
    float s = 0.f;
    for (int i = threadIdx.x; i < CIN * KW; i += blockDim.x) {
        float t = vp[i];
        s += t * t;
    }
    __shared__ float red[256];
    red[threadIdx.x] = s;
    __syncthreads();
    for (int o = 128; o > 0; o >>= 1) {
        if (threadIdx.x < o) red[threadIdx.x] += red[threadIdx.x + o];
        __syncthreads();
    }
    float scale = g[co] * rsqrtf(red[0]);
    for (int i = threadIdx.x; i < CIN * KW; i += blockDim.x)
        g_wn[(size_t)co * (CIN * KW) + i] = vp[i] * scale;
}

// ================= causal conv as 5 shifted GEMMs (bf16x3 tensor core) ==========
__global__ void __launch_bounds__(256) conv_kernel(const float* __restrict__ x,
                                                   const float* __restrict__ bias) {
    SMEM_DECL();
    int tid = threadIdx.x, lane = tid & 31, wid = tid >> 5;
    int wm = (wid & 1) * 64, wn = (wid >> 1) * 32;
    int l0 = blockIdx.x * 128, co0 = blockIdx.y * 128, b = blockIdx.z;
    STAGE_IDX();
    ACC_INIT();
    float2 sa[4], sb[4];
    const int NC = 160;  // 5 taps * 32 ci-chunks of 16

    auto prefetch = [&](int c) {
        int t = c >> 5, ci0 = (c & 31) << 4;
        int xp = l0 + crow + t - 4;
#pragma unroll
        for (int s = 0; s < 4; ++s) {
            int kp = ckp0 + s;
            size_t base = (size_t)(co0 + crow) * (CIN * KW) + (ci0 + 2 * kp) * KW + t;
            sa[s].x = g_wn[base];
            sa[s].y = g_wn[base + KW];
            if (xp >= 0) {
                size_t xb = ((size_t)b * CIN + ci0 + 2 * kp) * Lr + xp;
                sb[s].x = x[xb];
                sb[s].y = x[xb + Lr];
            } else {
                sb[s] = make_float2(0.f, 0.f);
            }
        }
    };

    prefetch(0);
    COMMIT(0)
    __syncthreads();
    for (int c = 0; c < NC; ++c) {
        if (c + 1 < NC) prefetch(c + 1);
        mma_chunk(Ah[c & 1], Al[c & 1], Bh[c & 1], Bl[c & 1], wm, wn, lane, acc);
        if (c + 1 < NC) { int nb = (c + 1) & 1; COMMIT(nb) }
        __syncthreads();
    }

    int r = lane >> 2;
#pragma unroll
    for (int i = 0; i < 4; ++i) {
        int co = co0 + wm + i * 16 + r;
        float b0 = bias[co], b1 = bias[co + 8];
#pragma unroll
        for (int j = 0; j < 4; ++j) {
            int l = l0 + wn + j * 8 + (lane & 3) * 2;
            *(float2*)&g_y[((size_t)b * COUT + co) * Lr + l] =
                make_float2(acc[i][j][0] + b0, acc[i][j][1] + b0);
            *(float2*)&g_y[((size_t)b * COUT + co + 8) * Lr + l] =
                make_float2(acc[i][j][2] + b1, acc[i][j][3] + b1);
        }
    }
}

// ================= GLU (vectorized) =================
__global__ void glu_kernel() {
    size_t p = (size_t)blockIdx.x * 256 + threadIdx.x;
    size_t e = p * 2;
    int l = (int)(e & 1023);
    size_t rest = e >> 10;
    int c = (int)(rest & 511);
    int b = (int)(rest >> 9);
    float2 a = *(const float2*)&g_y[((size_t)b * COUT + c) * Lr + l];
    float2 g = *(const float2*)&g_y[((size_t)b * COUT + c + HALF) * Lr + l];
    float2 r;
    r.x = a.x * (1.f / (1.f + expf(-g.x)));
    r.y = a.y * (1.f / (1.f + expf(-g.y)));
    *(float2*)&g_h[e] = r;
}

// ================= fc1: q = h^T W1^T + b1 + we =================
__global__ void __launch_bounds__(256) fc1_kernel(const float* __restrict__ w,
                                                  const float* __restrict__ bias,
                                                  const float* __restrict__ we) {
    SMEM_DECL();
    int tid = threadIdx.x, lane = tid & 31, wid = tid >> 5;
    int wm = (wid & 1) * 64, wn = (wid >> 1) * 32;
    int a0 = blockIdx.x * 128, m0 = blockIdx.y * 128;
    int b = m0 >> 10, l0 = m0 & 1023;
    STAGE_IDX();
    ACC_INIT();
    float2 sa[4], sb[4];
    const int NC = DW / 16;

    auto prefetch = [&](int c) {
        int k0 = c * 16;
#pragma unroll
        for (int s = 0; s < 4; ++s) {
            int kp = ckp0 + s;
            size_t hb = ((size_t)b * HALF + k0 + 2 * kp) * Lr + l0 + crow;
            sa[s].x = g_h[hb];
            sa[s].y = g_h[hb + Lr];
            sb[s] = *(const float2*)&w[(size_t)(a0 + crow) * DW + k0 + 2 * kp];
        }
    };

    prefetch(0);
    COMMIT(0)
    __syncthreads();
    for (int c = 0; c < NC; ++c) {
        if (c + 1 < NC) prefetch(c + 1);
        mma_chunk(Ah[c & 1], Al[c & 1], Bh[c & 1], Bl[c & 1], wm, wn, lane, acc);
        if (c + 1 < NC) { int nb = (c + 1) & 1; COMMIT(nb) }
        __syncthreads();
    }

    int r = lane >> 2;
#pragma unroll
    for (int i = 0; i < 4; ++i) {
        int m = m0 + wm + i * 16 + r;
#pragma unroll
        for (int j = 0; j < 4; ++j) {
            int a = a0 + wn + j * 8 + (lane & 3) * 2;
            float2 bb = *(const float2*)&bias[a];
            float2 w0 = *(const float2*)&we[(size_t)m * DW + a];
            float2 w1 = *(const float2*)&we[(size_t)(m + 8) * DW + a];
            *(float2*)&g_q[(size_t)m * DW + a] =
                make_float2(acc[i][j][0] + bb.x + w0.x, acc[i][j][1] + bb.y + w0.y);
            *(float2*)&g_q[(size_t)(m + 8) * DW + a] =
                make_float2(acc[i][j][2] + bb.x + w1.x, acc[i][j][3] + bb.y + w1.y);
        }
    }
}

// ================= score = q @ feat =================
__global__ void __launch_bounds__(256) score_kernel(const float* __restrict__ feat) {
    SMEM_DECL();
    int tid = threadIdx.x, lane = tid & 31, wid = tid >> 5;
    int wm = (wid & 1) * 64, wn = (wid >> 1) * 32;
    int p0 = blockIdx.x * 128, m0 = blockIdx.y * 128;
    int b = m0 >> 10;
    STAGE_IDX();
    ACC_INIT();
    float2 sa[4], sb[4];
    const int NC = DW / 16;

    auto prefetch = [&](int c) {
        int k0 = c * 16;
        int pp = p0 + crow;
#pragma unroll
        for (int s = 0; s < 4; ++s) {
            int kp = ckp0 + s;
            sa[s] = *(const float2*)&g_q[(size_t)(m0 + crow) * DW + k0 + 2 * kp];
            if (pp < HW) {
                size_t fb = ((size_t)b * DW + k0 + 2 * kp) * HW + pp;
                sb[s].x = feat[fb];
                sb[s].y = feat[fb + HW];
            } else {
                sb[s] = make_float2(0.f, 0.f);
            }
        }
    };

    prefetch(0);
    COMMIT(0)
    __syncthreads();
    for (int c = 0; c < NC; ++c) {
        if (c + 1 < NC) prefetch(c + 1);
        mma_chunk(Ah[c & 1], Al[c & 1], Bh[c & 1], Bl[c & 1], wm, wn, lane, acc);
        if (c + 1 < NC) { int nb = (c + 1) & 1; COMMIT(nb) }
        __syncthreads();
    }

    int r = lane >> 2;
#pragma unroll
    for (int i = 0; i < 4; ++i) {
        int m = m0 + wm + i * 16 + r;
#pragma unroll
        for (int j = 0; j < 4; ++j) {
            int p = p0 + wn + j * 8 + (lane & 3) * 2;
            if (p < HW) {
                *(float2*)&g_score[(size_t)m * HW + p] =
                    make_float2(acc[i][j][0], acc[i][j][1]);
                *(float2*)&g_score[(size_t)(m + 8) * HW + p] =
                    make_float2(acc[i][j][2], acc[i][j][3]);
            }
        }
    }
}

// ================= softmax over 196 (one warp per row) =================
__global__ void softmax_kernel(float* __restrict__ attn) {
    int warp = (blockIdx.x * blockDim.x + threadIdx.x) >> 5;
    int lane = threadIdx.x & 31;
    if (warp >= Bn * Lr) return;
    const float* sp = g_score + (size_t)warp * HW;
    float v[7];
    float mx = -1e30f;
#pragma unroll
    for (int i = 0; i < 7; ++i) {
        int p = lane + 32 * i;
        v[i] = (p < HW) ? sp[p] : -1e30f;
        mx = fmaxf(mx, v[i]);
    }
#pragma unroll
    for (int o = 16; o > 0; o >>= 1) mx = fmaxf(mx, __shfl_xor_sync(0xffffffffu, mx, o));
    float sum = 0.f;
#pragma unroll
    for (int i = 0; i < 7; ++i) {
        int p = lane + 32 * i;
        v[i] = (p < HW) ? expf(v[i] - mx) : 0.f;
        sum += v[i];
    }
#pragma unroll
    for (int o = 16; o > 0; o >>= 1) sum += __shfl_xor_sync(0xffffffffu, sum, o);
    float inv = 1.f / sum;
#pragma unroll
    for (int i = 0; i < 7; ++i) {
        int p = lane + 32 * i;
        if (p < HW) attn[(size_t)warp * HW + p] = v[i] * inv;
    }
}

// ================= ctx = attn @ feat^T =================
__global__ void __launch_bounds__(256) ctx_kernel(const float* __restrict__ attn,
                                                  const float* __restrict__ feat) {
    SMEM_DECL();
    int tid = threadIdx.x, lane = tid & 31, wid = tid >> 5;
    int wm = (wid & 1) * 64, wn = (wid >> 1) * 32;
    int a0 = blockIdx.x * 128, m0 = blockIdx.y * 128;
    int b = m0 >> 10;
    STAGE_IDX();
    ACC_INIT();
    float2 sa[4], sb[4];
    const int NC = 13;  // ceil(196/16)

    auto prefetch = [&](int c) {
        int k0 = c * 16;
#pragma unroll
        for (int s = 0; s < 4; ++s) {
            int kk = k0 + 2 * (ckp0 + s);
            if (kk < HW) {  // pairs fully valid or fully invalid (HW even)
                sa[s] = *(const float2*)&attn[(size_t)(m0 + crow) * HW + kk];
                sb[s] = *(const float2*)&feat[((size_t)b * DW + a0 + crow) * HW + kk];
            } else {
                sa[s] = make_float2(0.f, 0.f);
                sb[s] = make_float2(0.f, 0.f);
            }
        }
    };

    prefetch(0);
    COMMIT(0)
    __syncthreads();
    for (int c = 0; c < NC; ++c) {
        if (c + 1 < NC) prefetch(c + 1);
        mma_chunk(Ah[c & 1], Al[c & 1], Bh[c & 1], Bl[c & 1], wm, wn, lane, acc);
        if (c + 1 < NC) { int nb = (c + 1) & 1; COMMIT(nb) }
        __syncthreads();
    }

    int r = lane >> 2;
#pragma unroll
    for (int i = 0; i < 4; ++i) {
        int m = m0 + wm + i * 16 + r;
#pragma unroll
        for (int j = 0; j < 4; ++j) {
            int a = a0 + wn + j * 8 + (lane & 3) * 2;
            *(float2*)&g_ctx[(size_t)m * DW + a] = make_float2(acc[i][j][0], acc[i][j][1]);
            *(float2*)&g_ctx[(size_t)(m + 8) * DW + a] = make_float2(acc[i][j][2], acc[i][j][3]);
        }
    }
}

// ================= fc2 + residuals, transposed output =================
__global__ void __launch_bounds__(256) fc2_kernel(const float* __restrict__ w,
                                                  const float* __restrict__ bias,
                                                  const float* __restrict__ x,
                                                  float* __restrict__ out) {
    SMEM_DECL();
    int tid = threadIdx.x, lane = tid & 31, wid = tid >> 5;
    int wm = (wid & 1) * 64, wn = (wid >> 1) * 32;
    int l0 = blockIdx.x * 128, c0 = blockIdx.y * 128, b = blockIdx.z;
    STAGE_IDX();
    ACC_INIT();
    float2 sa[4], sb[4];
    const int NC = DW / 16;

    auto prefetch = [&](int c) {
        int k0 = c * 16;
#pragma unroll
        for (int s = 0; s < 4; ++s) {
            int kp = ckp0 + s;
            sa[s] = *(const float2*)&w[(size_t)(c0 + crow) * DW + k0 + 2 * kp];
            sb[s] = *(const float2*)&g_ctx[((size_t)b * Lr + l0 + crow) * DW + k0 + 2 * kp];
        }
    };

    prefetch(0);
    COMMIT(0)
    __syncthreads();
    for (int c = 0; c < NC; ++c) {
        if (c + 1 < NC) prefetch(c + 1);
        mma_chunk(Ah[c & 1], Al[c & 1], Bh[c & 1], Bl[c & 1], wm, wn, lane, acc);
        if (c + 1 < NC) { int nb = (c + 1) & 1; COMMIT(nb) }
        __syncthreads();
    }

    int r = lane >> 2;
#pragma unroll
    for (int i = 0; i < 4; ++i) {
        int cc = c0 + wm + i * 16 + r;
        float b0 = bias[cc], b1 = bias[cc + 8];
#pragma unroll
        for (int j = 0; j < 4; ++j) {
            int l = l0 + wn + j * 8 + (lane & 3) * 2;
            size_t o0 = ((size_t)b * HALF + cc) * Lr + l;
            size_t o1 = ((size_t)b * HALF + cc + 8) * Lr + l;
            float2 h0 = *(const float2*)&g_h[o0];
            float2 x0 = *(const float2*)&x[o0];
            float2 h1 = *(const float2*)&g_h[o1];
            float2 x1 = *(const float2*)&x[o1];
            *(float2*)&out[o0] = make_float2(acc[i][j][0] + b0 + h0.x + x0.x,
                                             acc[i][j][1] + b0 + h0.y + x0.y);
            *(float2*)&out[o1] = make_float2(acc[i][j][2] + b1 + h1.x + x1.x,
                                             acc[i][j][3] + b1 + h1.y + x1.y);
        }
    }
}

// ================= launch =================
extern "C" void kernel_launch(void* const* d_in, const int* in_sizes, int n_in,
                              void* d_out, int out_size) {
    const float* x      = (const float*)d_in[0];
    const float* we     = (const float*)d_in[1];
    const float* img    = (const float*)d_in[2];
    // d_in[3] prev_attn unused by reference
    const float* conv_v = (const float*)d_in[4];
    const float* conv_g = (const float*)d_in[5];
    const float* conv_b = (const float*)d_in[6];
    const float* fc1_w  = (const float*)d_in[7];
    const float* fc1_b  = (const float*)d_in[8];
    const float* fc2_w  = (const float*)d_in[9];
    const float* fc2_b  = (const float*)d_in[10];

    float* out = (float*)d_out;
    const size_t SZ_OUT = (size_t)Bn * HALF * Lr;  // 8388608
    const size_t SZ_WE  = (size_t)Bn * Lr * DW;    // 8388608
    const size_t SZ_IMG = (size_t)Bn * DW * HW;    // 1605632
    float* out_we   = out + SZ_OUT;
    float* out_img  = out_we + SZ_WE;
    float* out_attn = out_img + SZ_IMG;

    wnorm_kernel<<<COUT, 256>>>(conv_v, conv_g);
    conv_kernel<<<dim3(Lr / 128, COUT / 128, Bn), 256>>>(x, conv_b);
    glu_kernel<<<(Bn * HALF * Lr) / 512, 256>>>();
    fc1_kernel<<<dim3(DW / 128, (Bn * Lr) / 128), 256>>>(fc1_w, fc1_b, we);
    score_kernel<<<dim3(2, (Bn * Lr) / 128), 256>>>(img);
    softmax_kernel<<<(Bn * Lr) / 8, 256>>>(out_attn);
    ctx_kernel<<<dim3(DW / 128, (Bn * Lr) / 128), 256>>>(out_attn, img);
    fc2_kernel<<<dim3(Lr / 128, HALF / 128, Bn), 256>>>(fc2_w, fc2_b, x, out);

    cudaMemcpyAsync(out_we, we, SZ_WE * sizeof(float), cudaMemcpyDeviceToDevice, 0);
    cudaMemcpyAsync(out_img, img, SZ_IMG * sizeof(float), cudaMemcpyDeviceToDevice, 0);
}

// round 11
// speedup vs baseline: 1.6177x; 1.6177x over previous
#include <cuda_runtime.h>
#include <math.h>

#define Bn   16
#define CIN  512
#define Lr   1024
#define COUT 1024
#define KW   5
#define DW   512
#define HW   196
#define HALF 512

typedef unsigned uint_t;

// ---- scratch (device globals; no allocation allowed) ----
__device__ float g_scale[COUT];                   // g / ||v|| per out channel
__device__ float g_wnT[KW * CIN * COUT];          // normalized weights, [t][ci][co]
__device__ float g_y[(size_t)Bn * COUT * Lr];     // conv output (pre-GLU)
__device__ float g_h[(size_t)Bn * HALF * Lr];     // GLU output / identity_attn
__device__ float g_q[(size_t)Bn * Lr * DW];       // fc1 output + word_embed
__device__ float g_score[(size_t)Bn * Lr * HW];
__device__ float g_ctx[(size_t)Bn * Lr * DW];

// ---- bf16x3 split helpers ----
__device__ __forceinline__ void split2(float v0, float v1, uint_t& hi, uint_t& lo) {
    asm("cvt.rn.bf16x2.f32 %0, %1, %2;" : "=r"(hi) : "f"(v1), "f"(v0));
    float h0 = __uint_as_float(hi << 16);
    float h1 = __uint_as_float(hi & 0xffff0000u);
    asm("cvt.rn.bf16x2.f32 %0, %1, %2;" : "=r"(lo) : "f"(v1 - h1), "f"(v0 - h0));
}

__device__ __forceinline__ void mma_bf16(float* c, const uint_t* a, const uint_t* b) {
    asm volatile(
        "mma.sync.aligned.m16n8k16.row.col.f32.bf16.bf16.f32 "
        "{%0,%1,%2,%3}, {%4,%5,%6,%7}, {%8,%9}, {%0,%1,%2,%3};"
        : "+f"(c[0]), "+f"(c[1]), "+f"(c[2]), "+f"(c[3])
        : "r"(a[0]), "r"(a[1]), "r"(a[2]), "r"(a[3]), "r"(b[0]), "r"(b[1]));
}

__device__ __forceinline__ void ldsm4(uint_t& r0, uint_t& r1, uint_t& r2, uint_t& r3,
                                      const uint_t* p) {
    uint_t a = (uint_t)__cvta_generic_to_shared(p);
    asm volatile("ldmatrix.sync.aligned.m8n8.x4.shared.b16 {%0,%1,%2,%3}, [%4];"
                 : "=r"(r0), "=r"(r1), "=r"(r2), "=r"(r3) : "r"(a));
}

#define PAD 12  // row stride words: {12r mod 32} covers all banks -> conflict-free

// One 16-wide k-chunk: warp computes 64x32 via 4x4 m16n8k16 tiles, 3-term bf16 split.
__device__ __forceinline__ void mma_chunk(const uint_t (*Ah)[PAD], const uint_t (*Al)[PAD],
                                          const uint_t (*Bh)[PAD], const uint_t (*Bl)[PAD],
                                          int wm, int wn, int lane, float acc[4][4][4]) {
    int l7 = lane & 7;
    int arow = ((lane >> 3) & 1) * 8 + l7;
    int acol = (lane >> 4) * 4;
    int brow = (lane >> 4) * 8 + l7;
    int bcol = ((lane >> 3) & 1) * 4;

    uint_t ah[4][4], al[4][4], bh[4][2], bl[4][2];
#pragma unroll
    for (int i = 0; i < 4; ++i) {
        int r0 = wm + i * 16;
        ldsm4(ah[i][0], ah[i][1], ah[i][2], ah[i][3], &Ah[r0 + arow][acol]);
        ldsm4(al[i][0], al[i][1], al[i][2], al[i][3], &Al[r0 + arow][acol]);
    }
#pragma unroll
    for (int jp = 0; jp < 2; ++jp) {
        int n0 = wn + jp * 16;
        ldsm4(bh[2 * jp][0], bh[2 * jp][1], bh[2 * jp + 1][0], bh[2 * jp + 1][1],
              &Bh[n0 + brow][bcol]);
        ldsm4(bl[2 * jp][0], bl[2 * jp][1], bl[2 * jp + 1][0], bl[2 * jp + 1][1],
              &Bl[n0 + brow][bcol]);
    }
#pragma unroll
    for (int i = 0; i < 4; ++i)
#pragma unroll
        for (int j = 0; j < 4; ++j) {
            mma_bf16(acc[i][j], ah[i], bh[j]);
            mma_bf16(acc[i][j], ah[i], bl[j]);
            mma_bf16(acc[i][j], al[i], bh[j]);
        }
}

#define ACC_INIT()                                    \
    float acc[4][4][4];                               \
    _Pragma("unroll") for (int i = 0; i < 4; ++i)     \
        _Pragma("unroll") for (int j = 0; j < 4; ++j) \
            _Pragma("unroll") for (int t = 0; t < 4; ++t) acc[i][j][t] = 0.f;

#define SMEM_DECL()                                     \
    __shared__ uint_t Ah[2][128][PAD], Al[2][128][PAD]; \
    __shared__ uint_t Bh[2][128][PAD], Bl[2][128][PAD];

// col-fast staging: thread owns smem row `col`, k-pairs kp = 2s+kq (s=0..3)
#define COL_IDX() int col = tid & 127, kq = tid >> 7;
// k-fast staging: thread owns rows r4, r4+64; float4 at k-offset 4*q4
#define K4_IDX() int r4 = tid >> 2, q4 = tid & 3;

#define STORE_PAIR(AH, AL, buf, row, kp, v)         \
    {                                               \
        uint_t hi_, lo_;                            \
        split2((v).x, (v).y, hi_, lo_);             \
        AH[buf][row][kp] = hi_;                     \
        AL[buf][row][kp] = lo_;                     \
    }

#define STORE_QUAD(AH, AL, buf, row, f4)                        \
    {                                                           \
        uint_t h0_, l0_, h1_, l1_;                              \
        split2((f4).x, (f4).y, h0_, l0_);                       \
        split2((f4).z, (f4).w, h1_, l1_);                       \
        *(uint2*)&AH[buf][row][2 * q4] = make_uint2(h0_, h1_);  \
        *(uint2*)&AL[buf][row][2 * q4] = make_uint2(l0_, l1_);  \
    }

// ================= weight-norm scale =================
__global__ void wnorm_scale_kernel(const float* __restrict__ v, const float* __restrict__ g) {
    int co = blockIdx.x;
    const float* vp = v + (size_t)co * (CIN * KW);
    float s = 0.f;
    for (int i = threadIdx.x; i < CIN * KW; i += blockDim.x) {
        float t = vp[i];
        s += t * t;
    }
    __shared__ float red[256];
    red[threadIdx.x] = s;
    __syncthreads();
    for (int o = 128; o > 0; o >>= 1) {
        if (threadIdx.x < o) red[threadIdx.x] += red[threadIdx.x + o];
        __syncthreads();
    }
    if (threadIdx.x == 0) g_scale[co] = g[co] * rsqrtf(red[0]);
}

// ================= weight transpose: g_wnT[t][ci][co] = v[co][ci][t]*scale =====
__global__ void wt_kernel(const float* __restrict__ v) {
    __shared__ float tile[32][33];
    int k0 = blockIdx.x * 32, c0 = blockIdx.y * 32;
    int tx = threadIdx.x, ty0 = threadIdx.y;
#pragma unroll
    for (int i = 0; i < 32; i += 8) {
        int ty = ty0 + i;
        tile[ty][tx] = v[(size_t)(c0 + ty) * (CIN * KW) + k0 + tx];
    }
    __syncthreads();
    float sc = g_scale[c0 + tx];
#pragma unroll
    for (int i = 0; i < 32; i += 8) {
        int ty = ty0 + i;
        int kidx = k0 + ty;
        int ci = kidx / KW, t = kidx % KW;
        // FIX: destination is (co = c0+tx, k = k0+ty) -> read tile[tx][ty]
        g_wnT[((size_t)t * CIN + ci) * COUT + c0 + tx] = tile[tx][ty] * sc;
    }
}

// ================= causal conv as 5 shifted GEMMs (bf16x3 tensor core) ==========
__global__ void __launch_bounds__(256) conv_kernel(const float* __restrict__ x,
                                                   const float* __restrict__ bias) {
    SMEM_DECL();
    int tid = threadIdx.x, lane = tid & 31, wid = tid >> 5;
    int wm = (wid & 1) * 64, wn = (wid >> 1) * 32;
    int l0 = blockIdx.x * 128, co0 = blockIdx.y * 128, b = blockIdx.z;
    COL_IDX();
    ACC_INIT();
    float2 sa[4], sb[4];
    const int NC = 160;  // 5 taps * 32 ci-chunks of 16

    auto prefetch = [&](int c) {
        int t = c >> 5, ci0 = (c & 31) << 4;
        int xp = l0 + col + t - 4;
#pragma unroll
        for (int s = 0; s < 4; ++s) {
            int kp = 2 * s + kq;
            int ci = ci0 + 2 * kp;
            size_t wb = ((size_t)t * CIN + ci) * COUT + co0 + col;
            sa[s].x = g_wnT[wb];
            sa[s].y = g_wnT[wb + COUT];
            if (xp >= 0) {
                size_t xb = ((size_t)b * CIN + ci) * Lr + xp;
                sb[s].x = x[xb];
                sb[s].y = x[xb + Lr];
            } else {
                sb[s] = make_float2(0.f, 0.f);
            }
        }
    };
    auto commit = [&](int buf) {
#pragma unroll
        for (int s = 0; s < 4; ++s) {
            int kp = 2 * s + kq;
            STORE_PAIR(Ah, Al, buf, col, kp, sa[s])
            STORE_PAIR(Bh, Bl, buf, col, kp, sb[s])
        }
    };

    prefetch(0);
    commit(0);
    __syncthreads();
    for (int c = 0; c < NC; ++c) {
        if (c + 1 < NC) prefetch(c + 1);
        mma_chunk(Ah[c & 1], Al[c & 1], Bh[c & 1], Bl[c & 1], wm, wn, lane, acc);
        if (c + 1 < NC) commit((c + 1) & 1);
        __syncthreads();
    }

    int r = lane >> 2;
#pragma unroll
    for (int i = 0; i < 4; ++i) {
        int co = co0 + wm + i * 16 + r;
        float b0 = bias[co], b1 = bias[co + 8];
#pragma unroll
        for (int j = 0; j < 4; ++j) {
            int l = l0 + wn + j * 8 + (lane & 3) * 2;
            *(float2*)&g_y[((size_t)b * COUT + co) * Lr + l] =
                make_float2(acc[i][j][0] + b0, acc[i][j][1] + b0);
            *(float2*)&g_y[((size_t)b * COUT + co + 8) * Lr + l] =
                make_float2(acc[i][j][2] + b1, acc[i][j][3] + b1);
        }
    }
}

// ================= GLU (vectorized) =================
__global__ void glu_kernel() {
    size_t p = (size_t)blockIdx.x * 256 + threadIdx.x;
    size_t e = p * 2;
    int l = (int)(e & 1023);
    size_t rest = e >> 10;
    int c = (int)(rest & 511);
    int b = (int)(rest >> 9);
    float2 a = *(const float2*)&g_y[((size_t)b * COUT + c) * Lr + l];
    float2 g = *(const float2*)&g_y[((size_t)b * COUT + c + HALF) * Lr + l];
    float2 r;
    r.x = a.x * (1.f / (1.f + expf(-g.x)));
    r.y = a.y * (1.f / (1.f + expf(-g.y)));
    *(float2*)&g_h[e] = r;
}

// ================= fc1: q = h^T W1^T + b1 + we =================
__global__ void __launch_bounds__(256) fc1_kernel(const float* __restrict__ w,
                                                  const float* __restrict__ bias,
                                                  const float* __restrict__ we) {
    SMEM_DECL();
    int tid = threadIdx.x, lane = tid & 31, wid = tid >> 5;
    int wm = (wid & 1) * 64, wn = (wid >> 1) * 32;
    int a0 = blockIdx.x * 128, m0 = blockIdx.y * 128;
    int b = m0 >> 10, l0 = m0 & 1023;
    COL_IDX();
    K4_IDX();
    ACC_INIT();
    float2 sa[4];
    float4 sbq[2];
    const int NC = DW / 16;

    auto prefetch = [&](int c) {
        int k0 = c * 16;
#pragma unroll
        for (int s = 0; s < 4; ++s) {
            int kp = 2 * s + kq;
            size_t hb = ((size_t)b * HALF + k0 + 2 * kp) * Lr + l0 + col;
            sa[s].x = g_h[hb];
            sa[s].y = g_h[hb + Lr];
        }
#pragma unroll
        for (int p = 0; p < 2; ++p)
            sbq[p] = *(const float4*)&w[(size_t)(a0 + r4 + 64 * p) * DW + k0 + 4 * q4];
    };
    auto commit = [&](int buf) {
#pragma unroll
        for (int s = 0; s < 4; ++s) {
            int kp = 2 * s + kq;
            STORE_PAIR(Ah, Al, buf, col, kp, sa[s])
        }
#pragma unroll
        for (int p = 0; p < 2; ++p) STORE_QUAD(Bh, Bl, buf, r4 + 64 * p, sbq[p])
    };

    prefetch(0);
    commit(0);
    __syncthreads();
    for (int c = 0; c < NC; ++c) {
        if (c + 1 < NC) prefetch(c + 1);
        mma_chunk(Ah[c & 1], Al[c & 1], Bh[c & 1], Bl[c & 1], wm, wn, lane, acc);
        if (c + 1 < NC) commit((c + 1) & 1);
        __syncthreads();
    }

    int r = lane >> 2;
#pragma unroll
    for (int i = 0; i < 4; ++i) {
        int m = m0 + wm + i * 16 + r;
#pragma unroll
        for (int j = 0; j < 4; ++j) {
            int a = a0 + wn + j * 8 + (lane & 3) * 2;
            float2 bb = *(const float2*)&bias[a];
            float2 w0 = *(const float2*)&we[(size_t)m * DW + a];
            float2 w1 = *(const float2*)&we[(size_t)(m + 8) * DW + a];
            *(float2*)&g_q[(size_t)m * DW + a] =
                make_float2(acc[i][j][0] + bb.x + w0.x, acc[i][j][1] + bb.y + w0.y);
            *(float2*)&g_q[(size_t)(m + 8) * DW + a] =
                make_float2(acc[i][j][2] + bb.x + w1.x, acc[i][j][3] + bb.y + w1.y);
        }
    }
}

// ================= score = q @ feat =================
__global__ void __launch_bounds__(256) score_kernel(const float* __restrict__ feat) {
    SMEM_DECL();
    int tid = threadIdx.x, lane = tid & 31, wid = tid >> 5;
    int wm = (wid & 1) * 64, wn = (wid >> 1) * 32;
    int p0 = blockIdx.x * 128, m0 = blockIdx.y * 128;
    int b = m0 >> 10;
    COL_IDX();
    K4_IDX();
    ACC_INIT();
    float4 saq[2];
    float2 sb[4];
    const int NC = DW / 16;

    auto prefetch = [&](int c) {
        int k0 = c * 16;
#pragma unroll
        for (int p = 0; p < 2; ++p)
            saq[p] = *(const float4*)&g_q[(size_t)(m0 + r4 + 64 * p) * DW + k0 + 4 * q4];
        int pp = p0 + col;
#pragma unroll
        for (int s = 0; s < 4; ++s) {
            int kp = 2 * s + kq;
            if (pp < HW) {
                size_t fb = ((size_t)b * DW + k0 + 2 * kp) * HW + pp;
                sb[s].x = feat[fb];
                sb[s].y = feat[fb + HW];
            } else {
                sb[s] = make_float2(0.f, 0.f);
            }
        }
    };
    auto commit = [&](int buf) {
#pragma unroll
        for (int p = 0; p < 2; ++p) STORE_QUAD(Ah, Al, buf, r4 + 64 * p, saq[p])
#pragma unroll
        for (int s = 0; s < 4; ++s) {
            int kp = 2 * s + kq;
            STORE_PAIR(Bh, Bl, buf, col, kp, sb[s])
        }
    };

    prefetch(0);
    commit(0);
    __syncthreads();
    for (int c = 0; c < NC; ++c) {
        if (c + 1 < NC) prefetch(c + 1);
        mma_chunk(Ah[c & 1], Al[c & 1], Bh[c & 1], Bl[c & 1], wm, wn, lane, acc);
        if (c + 1 < NC) commit((c + 1) & 1);
        __syncthreads();
    }

    int r = lane >> 2;
#pragma unroll
    for (int i = 0; i < 4; ++i) {
        int m = m0 + wm + i * 16 + r;
#pragma unroll
        for (int j = 0; j < 4; ++j) {
            int p = p0 + wn + j * 8 + (lane & 3) * 2;
            if (p < HW) {
                *(float2*)&g_score[(size_t)m * HW + p] =
                    make_float2(acc[i][j][0], acc[i][j][1]);
                *(float2*)&g_score[(size_t)(m + 8) * HW + p] =
                    make_float2(acc[i][j][2], acc[i][j][3]);
            }
        }
    }
}

// ================= softmax over 196 (one warp per row) =================
__global__ void softmax_kernel(float* __restrict__ attn) {
    int warp = (blockIdx.x * blockDim.x + threadIdx.x) >> 5;
    int lane = threadIdx.x & 31;
    if (warp >= Bn * Lr) return;
    const float* sp = g_score + (size_t)warp * HW;
    float v[7];
    float mx = -1e30f;
#pragma unroll
    for (int i = 0; i < 7; ++i) {
        int p = lane + 32 * i;
        v[i] = (p < HW) ? sp[p] : -1e30f;
        mx = fmaxf(mx, v[i]);
    }
#pragma unroll
    for (int o = 16; o > 0; o >>= 1) mx = fmaxf(mx, __shfl_xor_sync(0xffffffffu, mx, o));
    float sum = 0.f;
#pragma unroll
    for (int i = 0; i < 7; ++i) {
        int p = lane + 32 * i;
        v[i] = (p < HW) ? expf(v[i] - mx) : 0.f;
        sum += v[i];
    }
#pragma unroll
    for (int o = 16; o > 0; o >>= 1) sum += __shfl_xor_sync(0xffffffffu, sum, o);
    float inv = 1.f / sum;
#pragma unroll
    for (int i = 0; i < 7; ++i) {
        int p = lane + 32 * i;
        if (p < HW) attn[(size_t)warp * HW + p] = v[i] * inv;
    }
}

// ================= ctx = attn @ feat^T =================
__global__ void __launch_bounds__(256) ctx_kernel(const float* __restrict__ attn,
                                                  const float* __restrict__ feat) {
    SMEM_DECL();
    int tid = threadIdx.x, lane = tid & 31, wid = tid >> 5;
    int wm = (wid & 1) * 64, wn = (wid >> 1) * 32;
    int a0 = blockIdx.x * 128, m0 = blockIdx.y * 128;
    int b = m0 >> 10;
    K4_IDX();
    ACC_INIT();
    float4 saq[2], sbq[2];
    const int NC = 13;  // ceil(196/16)

    auto prefetch = [&](int c) {
        int kk = c * 16 + 4 * q4;
        bool ok = kk < HW;  // 196 % 4 == 0: float4 fully valid or fully invalid
#pragma unroll
        for (int p = 0; p < 2; ++p) {
            if (ok) {
                saq[p] = *(const float4*)&attn[(size_t)(m0 + r4 + 64 * p) * HW + kk];
                sbq[p] = *(const float4*)&feat[((size_t)b * DW + a0 + r4 + 64 * p) * HW + kk];
            } else {
                saq[p] = make_float4(0.f, 0.f, 0.f, 0.f);
                sbq[p] = make_float4(0.f, 0.f, 0.f, 0.f);
            }
        }
    };
    auto commit = [&](int buf) {
#pragma unroll
        for (int p = 0; p < 2; ++p) {
            STORE_QUAD(Ah, Al, buf, r4 + 64 * p, saq[p])
            STORE_QUAD(Bh, Bl, buf, r4 + 64 * p, sbq[p])
        }
    };

    prefetch(0);
    commit(0);
    __syncthreads();
    for (int c = 0; c < NC; ++c) {
        if (c + 1 < NC) prefetch(c + 1);
        mma_chunk(Ah[c & 1], Al[c & 1], Bh[c & 1], Bl[c & 1], wm, wn, lane, acc);
        if (c + 1 < NC) commit((c + 1) & 1);
        __syncthreads();
    }

    int r = lane >> 2;
#pragma unroll
    for (int i = 0; i < 4; ++i) {
        int m = m0 + wm + i * 16 + r;
#pragma unroll
        for (int j = 0; j < 4; ++j) {
            int a = a0 + wn + j * 8 + (lane & 3) * 2;
            *(float2*)&g_ctx[(size_t)m * DW + a] = make_float2(acc[i][j][0], acc[i][j][1]);
            *(float2*)&g_ctx[(size_t)(m + 8) * DW + a] = make_float2(acc[i][j][2], acc[i][j][3]);
        }
    }
}

// ================= fc2 + residuals, transposed output =================
__global__ void __launch_bounds__(256) fc2_kernel(const float* __restrict__ w,
                                                  const float* __restrict__ bias,
                                                  const float* __restrict__ x,
                                                  float* __restrict__ out) {
    SMEM_DECL();
    int tid = threadIdx.x, lane = tid & 31, wid = tid >> 5;
    int wm = (wid & 1) * 64, wn = (wid >> 1) * 32;
    int l0 = blockIdx.x * 128, c0 = blockIdx.y * 128, b = blockIdx.z;
    K4_IDX();
    ACC_INIT();
    float4 saq[2], sbq[2];
    const int NC = DW / 16;

    auto prefetch = [&](int c) {
        int k0 = c * 16 + 4 * q4;
#pragma unroll
        for (int p = 0; p < 2; ++p) {
            saq[p] = *(const float4*)&w[(size_t)(c0 + r4 + 64 * p) * DW + k0];
            sbq[p] = *(const float4*)&g_ctx[((size_t)b * Lr + l0 + r4 + 64 * p) * DW + k0];
        }
    };
    auto commit = [&](int buf) {
#pragma unroll
        for (int p = 0; p < 2; ++p) {
            STORE_QUAD(Ah, Al, buf, r4 + 64 * p, saq[p])
            STORE_QUAD(Bh, Bl, buf, r4 + 64 * p, sbq[p])
        }
    };

    prefetch(0);
    commit(0);
    __syncthreads();
    for (int c = 0; c < NC; ++c) {
        if (c + 1 < NC) prefetch(c + 1);
        mma_chunk(Ah[c & 1], Al[c & 1], Bh[c & 1], Bl[c & 1], wm, wn, lane, acc);
        if (c + 1 < NC) commit((c + 1) & 1);
        __syncthreads();
    }

    int r = lane >> 2;
#pragma unroll
    for (int i = 0; i < 4; ++i) {
        int cc = c0 + wm + i * 16 + r;
        float b0 = bias[cc], b1 = bias[cc + 8];
#pragma unroll
        for (int j = 0; j < 4; ++j) {
            int l = l0 + wn + j * 8 + (lane & 3) * 2;
            size_t o0 = ((size_t)b * HALF + cc) * Lr + l;
            size_t o1 = ((size_t)b * HALF + cc + 8) * Lr + l;
            float2 h0 = *(const float2*)&g_h[o0];
            float2 x0 = *(const float2*)&x[o0];
            float2 h1 = *(const float2*)&g_h[o1];
            float2 x1 = *(const float2*)&x[o1];
            *(float2*)&out[o0] = make_float2(acc[i][j][0] + b0 + h0.x + x0.x,
                                             acc[i][j][1] + b0 + h0.y + x0.y);
            *(float2*)&out[o1] = make_float2(acc[i][j][2] + b1 + h1.x + x1.x,
                                             acc[i][j][3] + b1 + h1.y + x1.y);
        }
    }
}

// ================= launch =================
extern "C" void kernel_launch(void* const* d_in, const int* in_sizes, int n_in,
                              void* d_out, int out_size) {
    const float* x      = (const float*)d_in[0];
    const float* we     = (const float*)d_in[1];
    const float* img    = (const float*)d_in[2];
    // d_in[3] prev_attn unused by reference
    const float* conv_v = (const float*)d_in[4];
    const float* conv_g = (const float*)d_in[5];
    const float* conv_b = (const float*)d_in[6];
    const float* fc1_w  = (const float*)d_in[7];
    const float* fc1_b  = (const float*)d_in[8];
    const float* fc2_w  = (const float*)d_in[9];
    const float* fc2_b  = (const float*)d_in[10];

    float* out = (float*)d_out;
    const size_t SZ_OUT = (size_t)Bn * HALF * Lr;  // 8388608
    const size_t SZ_WE  = (size_t)Bn * Lr * DW;    // 8388608
    const size_t SZ_IMG = (size_t)Bn * DW * HW;    // 1605632
    float* out_we   = out + SZ_OUT;
    float* out_img  = out_we + SZ_WE;
    float* out_attn = out_img + SZ_IMG;

    wnorm_scale_kernel<<<COUT, 256>>>(conv_v, conv_g);
    wt_kernel<<<dim3((CIN * KW) / 32, COUT / 32), dim3(32, 8)>>>(conv_v);
    conv_kernel<<<dim3(Lr / 128, COUT / 128, Bn), 256>>>(x, conv_b);
    glu_kernel<<<(Bn * HALF * Lr) / 512, 256>>>();
    fc1_kernel<<<dim3(DW / 128, (Bn * Lr) / 128), 256>>>(fc1_w, fc1_b, we);
    score_kernel<<<dim3(2, (Bn * Lr) / 128), 256>>>(img);
    softmax_kernel<<<(Bn * Lr) / 8, 256>>>(out_attn);
    ctx_kernel<<<dim3(DW / 128, (Bn * Lr) / 128), 256>>>(out_attn, img);
    fc2_kernel<<<dim3(Lr / 128, HALF / 128, Bn), 256>>>(fc2_w, fc2_b, x, out);

    cudaMemcpyAsync(out_we, we, SZ_WE * sizeof(float), cudaMemcpyDeviceToDevice, 0);
    cudaMemcpyAsync(out_img, img, SZ_IMG * sizeof(float), cudaMemcpyDeviceToDevice, 0);
}

// round 13
// speedup vs baseline: 1.7379x; 1.0743x over previous
#include <cuda_runtime.h>
#include <math.h>

#define Bn   16
#define CIN  512
#define Lr   1024
#define COUT 1024
#define KW   5
#define DW   512
#define HW   196
#define HALF 512

typedef unsigned uint_t;

// ---- scratch (device globals; no allocation allowed) ----
__device__ float g_scale[COUT];
__device__ float g_y[(size_t)Bn * COUT * Lr];      // conv output (pre-GLU)
__device__ float g_h[(size_t)Bn * HALF * Lr];      // GLU output (fp32, fc2 residual)
__device__ float g_score[(size_t)Bn * Lr * HW];

// pre-split bf16 hi/lo planes (k-fast uint = bf16x2 pair)
__device__ __align__(16) uint_t wA_hi[COUT * 1280], wA_lo[COUT * 1280];          // conv A [co][k'=t*512+ci, /2]
__device__ __align__(16) uint_t xT_hi[(size_t)Bn * Lr * 256], xT_lo[(size_t)Bn * Lr * 256];   // conv B [b][l][ci/2]
__device__ __align__(16) uint_t hT_hi[(size_t)Bn * Lr * 256], hT_lo[(size_t)Bn * Lr * 256];   // fc1 A [b][l][c/2]
__device__ __align__(16) uint_t w1_hi[DW * 256], w1_lo[DW * 256];                // fc1 B [a][c/2]
__device__ __align__(16) uint_t qP_hi[(size_t)Bn * Lr * 256], qP_lo[(size_t)Bn * Lr * 256];   // score A [m][a/2]
__device__ __align__(16) uint_t fT_hi[(size_t)Bn * 256 * 256], fT_lo[(size_t)Bn * 256 * 256]; // score B [b][p(pad256)][dw/2]
__device__ __align__(16) uint_t aP_hi[(size_t)Bn * Lr * 104], aP_lo[(size_t)Bn * Lr * 104];   // ctx A [m][p/2 pad104]
__device__ __align__(16) uint_t fC_hi[(size_t)Bn * DW * 104], fC_lo[(size_t)Bn * DW * 104];   // ctx B [b][a][p/2 pad104]
__device__ __align__(16) uint_t cP_hi[(size_t)Bn * Lr * 256], cP_lo[(size_t)Bn * Lr * 256];   // fc2 B [m][a/2]
__device__ __align__(16) uint_t w2_hi[HALF * 256], w2_lo[HALF * 256];            // fc2 A [c][a/2]

// ---- bf16x3 split helper ----
__device__ __forceinline__ void split2(float v0, float v1, uint_t& hi, uint_t& lo) {
    asm("cvt.rn.bf16x2.f32 %0, %1, %2;" : "=r"(hi) : "f"(v1), "f"(v0));
    float h0 = __uint_as_float(hi << 16);
    float h1 = __uint_as_float(hi & 0xffff0000u);
    asm("cvt.rn.bf16x2.f32 %0, %1, %2;" : "=r"(lo) : "f"(v1 - h1), "f"(v0 - h0));
}

__device__ __forceinline__ void mma_bf16(float* c, const uint_t* a, const uint_t* b) {
    asm volatile(
        "mma.sync.aligned.m16n8k16.row.col.f32.bf16.bf16.f32 "
        "{%0,%1,%2,%3}, {%4,%5,%6,%7}, {%8,%9}, {%0,%1,%2,%3};"
        : "+f"(c[0]), "+f"(c[1]), "+f"(c[2]), "+f"(c[3])
        : "r"(a[0]), "r"(a[1]), "r"(a[2]), "r"(a[3]), "r"(b[0]), "r"(b[1]));
}

__device__ __forceinline__ void ldsm4(uint_t& r0, uint_t& r1, uint_t& r2, uint_t& r3,
                                      const uint_t* p) {
    uint_t a = (uint_t)__cvta_generic_to_shared(p);
    asm volatile("ldmatrix.sync.aligned.m8n8.x4.shared.b16 {%0,%1,%2,%3}, [%4];"
                 : "=r"(r0), "=r"(r1), "=r"(r2), "=r"(r3) : "r"(a));
}

__device__ __forceinline__ void cpa16(uint_t sdst, const void* g, int ok) {
    asm volatile("cp.async.cg.shared.global [%0], [%1], 16, %2;"
                 :: "r"(sdst), "l"(g), "r"(ok ? 16 : 0) : "memory");
}
#define CP_COMMIT() asm volatile("cp.async.commit_group;" ::: "memory")
#define CP_WAIT2()  asm volatile("cp.async.wait_group 2;" ::: "memory")

#define PAD 12        // row stride words: 48B rows keep 16B slots conflict-free
#define STAGE 6144    // uints per stage: 4 planes * 128 rows * PAD
#define DSMEM_BYTES (4 * STAGE * 4)

// One 16-wide k-chunk: warp computes 64x32 via 4x4 m16n8k16 tiles, 3-term bf16 split.
__device__ __forceinline__ void mma_chunk(const uint_t (*Ah)[PAD], const uint_t (*Al)[PAD],
                                          const uint_t (*Bh)[PAD], const uint_t (*Bl)[PAD],
                                          int wm, int wn, int lane, float acc[4][4][4]) {
    int l7 = lane & 7;
    int arow = ((lane >> 3) & 1) * 8 + l7;
    int acol = (lane >> 4) * 4;
    int brow = (lane >> 4) * 8 + l7;
    int bcol = ((lane >> 3) & 1) * 4;

    uint_t ah[4][4], al[4][4], bh[4][2], bl[4][2];
#pragma unroll
    for (int i = 0; i < 4; ++i) {
        int r0 = wm + i * 16;
        ldsm4(ah[i][0], ah[i][1], ah[i][2], ah[i][3], &Ah[r0 + arow][acol]);
        ldsm4(al[i][0], al[i][1], al[i][2], al[i][3], &Al[r0 + arow][acol]);
    }
#pragma unroll
    for (int jp = 0; jp < 2; ++jp) {
        int n0 = wn + jp * 16;
        ldsm4(bh[2 * jp][0], bh[2 * jp][1], bh[2 * jp + 1][0], bh[2 * jp + 1][1],
              &Bh[n0 + brow][bcol]);
        ldsm4(bl[2 * jp][0], bl[2 * jp][1], bl[2 * jp + 1][0], bl[2 * jp + 1][1],
              &Bl[n0 + brow][bcol]);
    }
#pragma unroll
    for (int i = 0; i < 4; ++i)
#pragma unroll
        for (int j = 0; j < 4; ++j) {
            mma_bf16(acc[i][j], ah[i], bh[j]);
            mma_bf16(acc[i][j], ah[i], bl[j]);
            mma_bf16(acc[i][j], al[i], bh[j]);
        }
}

#define ACC_INIT()                                    \
    float acc[4][4][4];                               \
    _Pragma("unroll") for (int i = 0; i < 4; ++i)     \
        _Pragma("unroll") for (int j = 0; j < 4; ++j) \
            _Pragma("unroll") for (int t = 0; t < 4; ++t) acc[i][j][t] = 0.f;

#define GEMM_PROLOG()                                            \
    extern __shared__ uint_t dsm[];                              \
    uint_t dsm_u32 = (uint_t)__cvta_generic_to_shared(dsm);      \
    int tid = threadIdx.x, lane = tid & 31, wid = tid >> 5;      \
    int wm = (wid & 1) * 64, wn = (wid >> 1) * 32;               \
    int row = tid >> 1, colw = (tid & 1) * 4;                    \
    ACC_INIT();

#define SLOT(c) (dsm_u32 + ((c & 3) * STAGE + row * PAD + colw) * 4)

#define PIPE_LOOP(NC)                                                       \
    issue(0); issue(1);                                                     \
    for (int c = 0; c < (NC); ++c) {                                        \
        issue(c + 2);                                                       \
        CP_WAIT2();                                                         \
        __syncthreads();                                                    \
        uint_t* S = dsm + (c & 3) * STAGE;                                  \
        mma_chunk((const uint_t(*)[PAD])S, (const uint_t(*)[PAD])(S + 1536),\
                  (const uint_t(*)[PAD])(S + 3072),                         \
                  (const uint_t(*)[PAD])(S + 4608), wm, wn, lane, acc);     \
    }

// ================= prepass kernels =================
__global__ void wnorm_scale_kernel(const float* __restrict__ v, const float* __restrict__ g) {
    int co = blockIdx.x;
    const float* vp = v + (size_t)co * (CIN * KW);
    float s = 0.f;
    for (int i = threadIdx.x; i < CIN * KW; i += blockDim.x) {
        float t = vp[i];
        s += t * t;
    }
    __shared__ float red[256];
    red[threadIdx.x] = s;
    __syncthreads();
    for (int o = 128; o > 0; o >>= 1) {
        if (threadIdx.x < o) red[threadIdx.x] += red[threadIdx.x + o];
        __syncthreads();
    }
    if (threadIdx.x == 0) g_scale[co] = g[co] * rsqrtf(red[0]);
}

// conv A planes: wA[co][k'=t*512+ci] from v[co][ci][t] * scale
__global__ void wsplitA_kernel(const float* __restrict__ v) {
    int co = blockIdx.x;
    float sc = g_scale[co];
    for (int kp = threadIdx.x; kp < 1280; kp += 256) {
        int t = kp >> 8, ci = (kp & 255) * 2;
        size_t s = (size_t)co * (CIN * KW) + (size_t)ci * KW + t;
        uint_t hi, lo;
        split2(v[s] * sc, v[s + KW] * sc, hi, lo);
        wA_hi[(size_t)co * 1280 + kp] = hi;
        wA_lo[(size_t)co * 1280 + kp] = lo;
    }
}

// transpose+split body: src [b][512][Lr] fp32 -> dst planes [b][l][256]
// (dhi/dlo are DEVICE-code symbol references from the wrappers below — never
//  host-passed; host-passing __device__ symbols was the R12 bug)
__device__ __forceinline__ void tsplit_body(const float* __restrict__ src,
                                            uint_t* __restrict__ dhi,
                                            uint_t* __restrict__ dlo) {
    __shared__ float tile[32][33];
    int l0 = blockIdx.x * 32, c0 = blockIdx.y * 32, b = blockIdx.z;
    int tx = threadIdx.x, ty0 = threadIdx.y;
#pragma unroll
    for (int i = 0; i < 32; i += 8)
        tile[ty0 + i][tx] = src[((size_t)b * 512 + c0 + ty0 + i) * Lr + l0 + tx];
    __syncthreads();
    int id = ty0 * 32 + tx;
#pragma unroll
    for (int rpt = 0; rpt < 2; ++rpt) {
        int item = id + 256 * rpt;
        int l = item >> 4, u = item & 15;
        uint_t hi, lo;
        split2(tile[2 * u][l], tile[2 * u + 1][l], hi, lo);
        size_t o = ((size_t)b * Lr + l0 + l) * 256 + c0 / 2 + u;
        dhi[o] = hi;
        dlo[o] = lo;
    }
}
__global__ void tsplit_x_kernel(const float* __restrict__ x) { tsplit_body(x, xT_hi, xT_lo); }
__global__ void tsplit_h_kernel() { tsplit_body(g_h, hT_hi, hT_lo); }

// k-fast split body: src [n][512] -> planes [n][256]
__device__ __forceinline__ void ksplit_body(const float* __restrict__ src,
                                            uint_t* __restrict__ dhi,
                                            uint_t* __restrict__ dlo) {
    int n = blockIdx.x, kp = threadIdx.x;
    float2 p = *(const float2*)&src[(size_t)n * DW + 2 * kp];
    uint_t hi, lo;
    split2(p.x, p.y, hi, lo);
    dhi[(size_t)n * 256 + kp] = hi;
    dlo[(size_t)n * 256 + kp] = lo;
}
__global__ void ksplit_w1_kernel(const float* __restrict__ w) { ksplit_body(w, w1_hi, w1_lo); }
__global__ void ksplit_w2_kernel(const float* __restrict__ w) { ksplit_body(w, w2_hi, w2_lo); }

// score B: img[b][dw][p] -> fT[b][p(pad256)][dw/2]
__global__ void fTsplit_kernel(const float* __restrict__ img) {
    __shared__ float tile[32][33];
    int p0 = blockIdx.x * 32, d0 = blockIdx.y * 32, b = blockIdx.z;
    int tx = threadIdx.x, ty0 = threadIdx.y;
#pragma unroll
    for (int i = 0; i < 32; i += 8) {
        int p = p0 + tx;
        tile[ty0 + i][tx] = (p < HW) ? img[((size_t)b * DW + d0 + ty0 + i) * HW + p] : 0.f;
    }
    __syncthreads();
    int id = ty0 * 32 + tx;
#pragma unroll
    for (int rpt = 0; rpt < 2; ++rpt) {
        int item = id + 256 * rpt;
        int p = item >> 4, u = item & 15;
        uint_t hi, lo;
        split2(tile[2 * u][p], tile[2 * u + 1][p], hi, lo);
        size_t o = ((size_t)b * 256 + p0 + p) * 256 + d0 / 2 + u;
        fT_hi[o] = hi;
        fT_lo[o] = lo;
    }
}

// ctx B: img[b][a][p] -> fC[b][a][p/2 pad104]
__global__ void fCsplit_kernel(const float* __restrict__ img) {
    int a = blockIdx.x, b = blockIdx.y, kp = threadIdx.x;
    if (kp >= 104) return;
    int p = 2 * kp;
    float v0 = (p < HW) ? img[((size_t)b * DW + a) * HW + p] : 0.f;
    float v1 = (p + 1 < HW) ? img[((size_t)b * DW + a) * HW + p + 1] : 0.f;
    uint_t hi, lo;
    split2(v0, v1, hi, lo);
    size_t o = ((size_t)b * DW + a) * 104 + kp;
    fC_hi[o] = hi;
    fC_lo[o] = lo;
}

// ctx A: attn[m][196] -> aP[m][104]
__global__ void aPsplit_kernel(const float* __restrict__ attn) {
    int m = blockIdx.x, kp = threadIdx.x;
    if (kp >= 104) return;
    int p = 2 * kp;
    float v0 = (p < HW) ? attn[(size_t)m * HW + p] : 0.f;
    float v1 = (p + 1 < HW) ? attn[(size_t)m * HW + p + 1] : 0.f;
    uint_t hi, lo;
    split2(v0, v1, hi, lo);
    aP_hi[(size_t)m * 104 + kp] = hi;
    aP_lo[(size_t)m * 104 + kp] = lo;
}

// ================= causal conv as 5 shifted GEMMs =================
__global__ void __launch_bounds__(256, 2) conv_kernel(const float* __restrict__ bias) {
    GEMM_PROLOG();
    int l0 = blockIdx.x * 128, co0 = blockIdx.y * 128, b = blockIdx.z;
    const int NC = 160;

    auto issue = [&](int c) {
        if (c < NC) {
            uint_t su = SLOT(c);
            int t = c >> 5;
            size_t ao = (size_t)(co0 + row) * 1280 + c * 8 + colw;
            cpa16(su, wA_hi + ao, 1);
            cpa16(su + 6144, wA_lo + ao, 1);
            int xr = l0 + row + t - 4;
            int ok = xr >= 0;
            size_t bo = ((size_t)b * Lr + (ok ? xr : 0)) * 256 + (c & 31) * 8 + colw;
            cpa16(su + 12288, xT_hi + bo, ok);
            cpa16(su + 18432, xT_lo + bo, ok);
        }
        CP_COMMIT();
    };

    PIPE_LOOP(NC)

    int r = lane >> 2;
#pragma unroll
    for (int i = 0; i < 4; ++i) {
        int co = co0 + wm + i * 16 + r;
        float b0 = bias[co], b1 = bias[co + 8];
#pragma unroll
        for (int j = 0; j < 4; ++j) {
            int l = l0 + wn + j * 8 + (lane & 3) * 2;
            *(float2*)&g_y[((size_t)b * COUT + co) * Lr + l] =
                make_float2(acc[i][j][0] + b0, acc[i][j][1] + b0);
            *(float2*)&g_y[((size_t)b * COUT + co + 8) * Lr + l] =
                make_float2(acc[i][j][2] + b1, acc[i][j][3] + b1);
        }
    }
}

// ================= GLU =================
__global__ void glu_kernel() {
    size_t p = (size_t)blockIdx.x * 256 + threadIdx.x;
    size_t e = p * 2;
    int l = (int)(e & 1023);
    size_t rest = e >> 10;
    int c = (int)(rest & 511);
    int b = (int)(rest >> 9);
    float2 a = *(const float2*)&g_y[((size_t)b * COUT + c) * Lr + l];
    float2 g = *(const float2*)&g_y[((size_t)b * COUT + c + HALF) * Lr + l];
    float2 r;
    r.x = a.x * (1.f / (1.f + expf(-g.x)));
    r.y = a.y * (1.f / (1.f + expf(-g.y)));
    *(float2*)&g_h[e] = r;
}

// ================= fc1: q = h^T W1^T + b1 + we -> q planes =================
__global__ void __launch_bounds__(256, 2) fc1_kernel(const float* __restrict__ bias,
                                                     const float* __restrict__ we) {
    GEMM_PROLOG();
    int a0 = blockIdx.x * 128, m0 = blockIdx.y * 128;
    int b = m0 >> 10, l0 = m0 & 1023;
    const int NC = 32;

    auto issue = [&](int c) {
        if (c < NC) {
            uint_t su = SLOT(c);
            size_t ao = ((size_t)b * Lr + l0 + row) * 256 + c * 8 + colw;
            cpa16(su, hT_hi + ao, 1);
            cpa16(su + 6144, hT_lo + ao, 1);
            size_t bo = (size_t)(a0 + row) * 256 + c * 8 + colw;
            cpa16(su + 12288, w1_hi + bo, 1);
            cpa16(su + 18432, w1_lo + bo, 1);
        }
        CP_COMMIT();
    };

    PIPE_LOOP(NC)

    int r = lane >> 2;
#pragma unroll
    for (int i = 0; i < 4; ++i) {
        int m = m0 + wm + i * 16 + r;
#pragma unroll
        for (int j = 0; j < 4; ++j) {
            int a = a0 + wn + j * 8 + (lane & 3) * 2;
            int ua = a >> 1;
            float2 bb = *(const float2*)&bias[a];
            float2 w0 = *(const float2*)&we[(size_t)m * DW + a];
            float2 w1v = *(const float2*)&we[(size_t)(m + 8) * DW + a];
            uint_t hi, lo;
            split2(acc[i][j][0] + bb.x + w0.x, acc[i][j][1] + bb.y + w0.y, hi, lo);
            qP_hi[(size_t)m * 256 + ua] = hi;
            qP_lo[(size_t)m * 256 + ua] = lo;
            split2(acc[i][j][2] + bb.x + w1v.x, acc[i][j][3] + bb.y + w1v.y, hi, lo);
            qP_hi[(size_t)(m + 8) * 256 + ua] = hi;
            qP_lo[(size_t)(m + 8) * 256 + ua] = lo;
        }
    }
}

// ================= score = q @ feat =================
__global__ void __launch_bounds__(256, 2) score_kernel() {
    GEMM_PROLOG();
    int p0 = blockIdx.x * 128, m0 = blockIdx.y * 128;
    int b = m0 >> 10;
    const int NC = 32;

    auto issue = [&](int c) {
        if (c < NC) {
            uint_t su = SLOT(c);
            size_t ao = (size_t)(m0 + row) * 256 + c * 8 + colw;
            cpa16(su, qP_hi + ao, 1);
            cpa16(su + 6144, qP_lo + ao, 1);
            size_t bo = ((size_t)b * 256 + p0 + row) * 256 + c * 8 + colw;
            cpa16(su + 12288, fT_hi + bo, 1);
            cpa16(su + 18432, fT_lo + bo, 1);
        }
        CP_COMMIT();
    };

    PIPE_LOOP(NC)

    int r = lane >> 2;
#pragma unroll
    for (int i = 0; i < 4; ++i) {
        int m = m0 + wm + i * 16 + r;
#pragma unroll
        for (int j = 0; j < 4; ++j) {
            int p = p0 + wn + j * 8 + (lane & 3) * 2;
            if (p < HW) {
                *(float2*)&g_score[(size_t)m * HW + p] =
                    make_float2(acc[i][j][0], acc[i][j][1]);
                *(float2*)&g_score[(size_t)(m + 8) * HW + p] =
                    make_float2(acc[i][j][2], acc[i][j][3]);
            }
        }
    }
}

// ================= softmax over 196 =================
__global__ void softmax_kernel(float* __restrict__ attn) {
    int warp = (blockIdx.x * blockDim.x + threadIdx.x) >> 5;
    int lane = threadIdx.x & 31;
    if (warp >= Bn * Lr) return;
    const float* sp = g_score + (size_t)warp * HW;
    float v[7];
    float mx = -1e30f;
#pragma unroll
    for (int i = 0; i < 7; ++i) {
        int p = lane + 32 * i;
        v[i] = (p < HW) ? sp[p] : -1e30f;
        mx = fmaxf(mx, v[i]);
    }
#pragma unroll
    for (int o = 16; o > 0; o >>= 1) mx = fmaxf(mx, __shfl_xor_sync(0xffffffffu, mx, o));
    float sum = 0.f;
#pragma unroll
    for (int i = 0; i < 7; ++i) {
        int p = lane + 32 * i;
        v[i] = (p < HW) ? expf(v[i] - mx) : 0.f;
        sum += v[i];
    }
#pragma unroll
    for (int o = 16; o > 0; o >>= 1) sum += __shfl_xor_sync(0xffffffffu, sum, o);
    float inv = 1.f / sum;
#pragma unroll
    for (int i = 0; i < 7; ++i) {
        int p = lane + 32 * i;
        if (p < HW) attn[(size_t)warp * HW + p] = v[i] * inv;
    }
}

// ================= ctx = attn @ feat^T -> ctx planes =================
__global__ void __launch_bounds__(256, 2) ctx_kernel() {
    GEMM_PROLOG();
    int a0 = blockIdx.x * 128, m0 = blockIdx.y * 128;
    int b = m0 >> 10;
    const int NC = 13;

    auto issue = [&](int c) {
        if (c < NC) {
            uint_t su = SLOT(c);
            size_t ao = (size_t)(m0 + row) * 104 + c * 8 + colw;
            cpa16(su, aP_hi + ao, 1);
            cpa16(su + 6144, aP_lo + ao, 1);
            size_t bo = ((size_t)b * DW + a0 + row) * 104 + c * 8 + colw;
            cpa16(su + 12288, fC_hi + bo, 1);
            cpa16(su + 18432, fC_lo + bo, 1);
        }
        CP_COMMIT();
    };

    PIPE_LOOP(NC)

    int r = lane >> 2;
#pragma unroll
    for (int i = 0; i < 4; ++i) {
        int m = m0 + wm + i * 16 + r;
#pragma unroll
        for (int j = 0; j < 4; ++j) {
            int a = a0 + wn + j * 8 + (lane & 3) * 2;
            int ua = a >> 1;
            uint_t hi, lo;
            split2(acc[i][j][0], acc[i][j][1], hi, lo);
            cP_hi[(size_t)m * 256 + ua] = hi;
            cP_lo[(size_t)m * 256 + ua] = lo;
            split2(acc[i][j][2], acc[i][j][3], hi, lo);
            cP_hi[(size_t)(m + 8) * 256 + ua] = hi;
            cP_lo[(size_t)(m + 8) * 256 + ua] = lo;
        }
    }
}

// ================= fc2 + residuals, transposed output =================
__global__ void __launch_bounds__(256, 2) fc2_kernel(const float* __restrict__ bias,
                                                     const float* __restrict__ x,
                                                     float* __restrict__ out) {
    GEMM_PROLOG();
    int l0 = blockIdx.x * 128, c0 = blockIdx.y * 128, b = blockIdx.z;
    const int NC = 32;

    auto issue = [&](int c) {
        if (c < NC) {
            uint_t su = SLOT(c);
            size_t ao = (size_t)(c0 + row) * 256 + c * 8 + colw;
            cpa16(su, w2_hi + ao, 1);
            cpa16(su + 6144, w2_lo + ao, 1);
            size_t bo = ((size_t)b * Lr + l0 + row) * 256 + c * 8 + colw;
            cpa16(su + 12288, cP_hi + bo, 1);
            cpa16(su + 18432, cP_lo + bo, 1);
        }
        CP_COMMIT();
    };

    PIPE_LOOP(NC)

    int r = lane >> 2;
#pragma unroll
    for (int i = 0; i < 4; ++i) {
        int cc = c0 + wm + i * 16 + r;
        float b0 = bias[cc], b1 = bias[cc + 8];
#pragma unroll
        for (int j = 0; j < 4; ++j) {
            int l = l0 + wn + j * 8 + (lane & 3) * 2;
            size_t o0 = ((size_t)b * HALF + cc) * Lr + l;
            size_t o1 = ((size_t)b * HALF + cc + 8) * Lr + l;
            float2 h0 = *(const float2*)&g_h[o0];
            float2 x0 = *(const float2*)&x[o0];
            float2 h1 = *(const float2*)&g_h[o1];
            float2 x1 = *(const float2*)&x[o1];
            *(float2*)&out[o0] = make_float2(acc[i][j][0] + b0 + h0.x + x0.x,
                                             acc[i][j][1] + b0 + h0.y + x0.y);
            *(float2*)&out[o1] = make_float2(acc[i][j][2] + b1 + h1.x + x1.x,
                                             acc[i][j][3] + b1 + h1.y + x1.y);
        }
    }
}

// ================= launch =================
extern "C" void kernel_launch(void* const* d_in, const int* in_sizes, int n_in,
                              void* d_out, int out_size) {
    const float* x      = (const float*)d_in[0];
    const float* we     = (const float*)d_in[1];
    const float* img    = (const float*)d_in[2];
    const float* conv_v = (const float*)d_in[4];
    const float* conv_g = (const float*)d_in[5];
    const float* conv_b = (const float*)d_in[6];
    const float* fc1_w  = (const float*)d_in[7];
    const float* fc1_b  = (const float*)d_in[8];
    const float* fc2_w  = (const float*)d_in[9];
    const float* fc2_b  = (const float*)d_in[10];

    float* out = (float*)d_out;
    const size_t SZ_OUT = (size_t)Bn * HALF * Lr;
    const size_t SZ_WE  = (size_t)Bn * Lr * DW;
    const size_t SZ_IMG = (size_t)Bn * DW * HW;
    float* out_we   = out + SZ_OUT;
    float* out_img  = out_we + SZ_WE;
    float* out_attn = out_img + SZ_IMG;

    cudaFuncSetAttribute(conv_kernel, cudaFuncAttributeMaxDynamicSharedMemorySize, DSMEM_BYTES);
    cudaFuncSetAttribute(fc1_kernel, cudaFuncAttributeMaxDynamicSharedMemorySize, DSMEM_BYTES);
    cudaFuncSetAttribute(score_kernel, cudaFuncAttributeMaxDynamicSharedMemorySize, DSMEM_BYTES);
    cudaFuncSetAttribute(ctx_kernel, cudaFuncAttributeMaxDynamicSharedMemorySize, DSMEM_BYTES);
    cudaFuncSetAttribute(fc2_kernel, cudaFuncAttributeMaxDynamicSharedMemorySize, DSMEM_BYTES);

    // prepass splits (all plane outputs referenced from DEVICE code only)
    wnorm_scale_kernel<<<COUT, 256>>>(conv_v, conv_g);
    wsplitA_kernel<<<COUT, 256>>>(conv_v);
    tsplit_x_kernel<<<dim3(Lr / 32, CIN / 32, Bn), dim3(32, 8)>>>(x);
    ksplit_w1_kernel<<<DW, 256>>>(fc1_w);
    ksplit_w2_kernel<<<HALF, 256>>>(fc2_w);
    fTsplit_kernel<<<dim3(8, DW / 32, Bn), dim3(32, 8)>>>(img);
    fCsplit_kernel<<<dim3(DW, Bn), 128>>>(img);

    conv_kernel<<<dim3(Lr / 128, COUT / 128, Bn), 256, DSMEM_BYTES>>>(conv_b);
    glu_kernel<<<(Bn * HALF * Lr) / 512, 256>>>();
    tsplit_h_kernel<<<dim3(Lr / 32, HALF / 32, Bn), dim3(32, 8)>>>();
    fc1_kernel<<<dim3(DW / 128, (Bn * Lr) / 128), 256, DSMEM_BYTES>>>(fc1_b, we);
    score_kernel<<<dim3(2, (Bn * Lr) / 128), 256, DSMEM_BYTES>>>();
    softmax_kernel<<<(Bn * Lr) / 8, 256>>>(out_attn);
    aPsplit_kernel<<<Bn * Lr, 128>>>(out_attn);
    ctx_kernel<<<dim3(DW / 128, (Bn * Lr) / 128), 256, DSMEM_BYTES>>>();
    fc2_kernel<<<dim3(Lr / 128, HALF / 128, Bn), 256, DSMEM_BYTES>>>(fc2_b, x, out);

    cudaMemcpyAsync(out_we, we, SZ_WE * sizeof(float), cudaMemcpyDeviceToDevice, 0);
    cudaMemcpyAsync(out_img, img, SZ_IMG * sizeof(float), cudaMemcpyDeviceToDevice, 0);
}

// round 15
// speedup vs baseline: 2.5419x; 1.4626x over previous
#include <cuda_runtime.h>
#include <math.h>

#define Bn   16
#define CIN  512
#define Lr   1024
#define COUT 1024
#define KW   5
#define DW   512
#define HW   196
#define HALF 512

typedef unsigned uint_t;

// ---- scratch (device globals; no allocation allowed) ----
__device__ float g_scale[COUT];
__device__ float g_y[(size_t)Bn * COUT * Lr];      // conv output (pre-GLU)
__device__ float g_h[(size_t)Bn * HALF * Lr];      // GLU output (fp32, fc2 residual)
__device__ float g_score[(size_t)Bn * Lr * HW];

// conv planes: fp16 (2-term split, no B_lo plane needed)
__device__ __align__(16) uint_t wH_hi[COUT * 1280], wH_lo[COUT * 1280];          // A [co][k'=t*256+ci/2]
__device__ __align__(16) uint_t xH_hi[(size_t)Bn * Lr * 256];                    // B [b][l][ci/2]
// bf16 hi/lo planes for the other GEMMs
__device__ __align__(16) uint_t hT_hi[(size_t)Bn * Lr * 256], hT_lo[(size_t)Bn * Lr * 256];   // fc1 A [b][l][c/2]
__device__ __align__(16) uint_t w1_hi[DW * 256], w1_lo[DW * 256];                // fc1 B [a][c/2]
__device__ __align__(16) uint_t qP_hi[(size_t)Bn * Lr * 256], qP_lo[(size_t)Bn * Lr * 256];   // score A [m][a/2]
__device__ __align__(16) uint_t fT_hi[(size_t)Bn * 256 * 256], fT_lo[(size_t)Bn * 256 * 256]; // score B [b][p pad256][dw/2]
__device__ __align__(16) uint_t aP_hi[(size_t)Bn * Lr * 104], aP_lo[(size_t)Bn * Lr * 104];   // ctx A [m][p/2 pad104]
__device__ __align__(16) uint_t fC_hi[(size_t)Bn * DW * 104], fC_lo[(size_t)Bn * DW * 104];   // ctx B [b][a][p/2]
__device__ __align__(16) uint_t cP_hi[(size_t)Bn * Lr * 256], cP_lo[(size_t)Bn * Lr * 256];   // fc2 B [m][a/2]
__device__ __align__(16) uint_t w2_hi[HALF * 256], w2_lo[HALF * 256];            // fc2 A [c][a/2]

// ---- split helpers ----
__device__ __forceinline__ void split2(float v0, float v1, uint_t& hi, uint_t& lo) {  // bf16
    asm("cvt.rn.bf16x2.f32 %0, %1, %2;" : "=r"(hi) : "f"(v1), "f"(v0));
    float h0 = __uint_as_float(hi << 16);
    float h1 = __uint_as_float(hi & 0xffff0000u);
    asm("cvt.rn.bf16x2.f32 %0, %1, %2;" : "=r"(lo) : "f"(v1 - h1), "f"(v0 - h0));
}
__device__ __forceinline__ void split2h(float v0, float v1, uint_t& hi, uint_t& lo) {  // fp16
    asm("cvt.rn.f16x2.f32 %0, %1, %2;" : "=r"(hi) : "f"(v1), "f"(v0));
    float h0, h1;
    asm("{\n\t.reg .b16 a,b;\n\tmov.b32 {a,b}, %2;\n\tcvt.f32.f16 %0, a;\n\tcvt.f32.f16 %1, b;\n\t}"
        : "=f"(h0), "=f"(h1) : "r"(hi));
    asm("cvt.rn.f16x2.f32 %0, %1, %2;" : "=r"(lo) : "f"(v1 - h1), "f"(v0 - h0));
}
__device__ __forceinline__ uint_t pack_h(float v0, float v1) {
    uint_t r;
    asm("cvt.rn.f16x2.f32 %0, %1, %2;" : "=r"(r) : "f"(v1), "f"(v0));
    return r;
}

__device__ __forceinline__ void mma_bf16(float* c, const uint_t* a, const uint_t* b) {
    asm volatile(
        "mma.sync.aligned.m16n8k16.row.col.f32.bf16.bf16.f32 "
        "{%0,%1,%2,%3}, {%4,%5,%6,%7}, {%8,%9}, {%0,%1,%2,%3};"
        : "+f"(c[0]), "+f"(c[1]), "+f"(c[2]), "+f"(c[3])
        : "r"(a[0]), "r"(a[1]), "r"(a[2]), "r"(a[3]), "r"(b[0]), "r"(b[1]));
}
__device__ __forceinline__ void mma_f16(float* c, const uint_t* a, const uint_t* b) {
    asm volatile(
        "mma.sync.aligned.m16n8k16.row.col.f32.f16.f16.f32 "
        "{%0,%1,%2,%3}, {%4,%5,%6,%7}, {%8,%9}, {%0,%1,%2,%3};"
        : "+f"(c[0]), "+f"(c[1]), "+f"(c[2]), "+f"(c[3])
        : "r"(a[0]), "r"(a[1]), "r"(a[2]), "r"(a[3]), "r"(b[0]), "r"(b[1]));
}

__device__ __forceinline__ void ldsm4r(uint_t* r, uint_t addr) {
    asm volatile("ldmatrix.sync.aligned.m8n8.x4.shared.b16 {%0,%1,%2,%3}, [%4];"
                 : "=r"(r[0]), "=r"(r[1]), "=r"(r[2]), "=r"(r[3]) : "r"(addr));
}

__device__ __forceinline__ void cpa16(uint_t sdst, const void* g, int ok) {
    asm volatile("cp.async.cg.shared.global [%0], [%1], 16, %2;"
                 :: "r"(sdst), "l"(g), "r"(ok ? 16 : 0) : "memory");
}
#define CP_COMMIT() asm volatile("cp.async.commit_group;" ::: "memory")
#define CP_WAIT1()  asm volatile("cp.async.wait_group 1;" ::: "memory")

// 64B rows + XOR swizzle keeps LDSM and cp.async 16B slots conflict-free
#define SWZ(o) ((o) ^ (((o) >> 3) & 0x70))

// generic (bf16, 4-plane) stage: planes at 0/8192/16384/24576, stage stride 32KB
#define GS_STRIDE 32768
#define DSMEM_G  (3 * GS_STRIDE)
// conv (fp16, 3-plane) stage: A_hi 0, A_lo 8192, B_hi 16384, stride 24KB
#define CS_STRIDE 24576
#define DSMEM_C  (3 * CS_STRIDE)

#define ACC_INIT()                                    \
    float acc[4][4][4];                               \
    _Pragma("unroll") for (int i = 0; i < 4; ++i)     \
        _Pragma("unroll") for (int j = 0; j < 4; ++j) \
            _Pragma("unroll") for (int t = 0; t < 4; ++t) acc[i][j][t] = 0.f;

#define GEMM_PROLOG()                                            \
    extern __shared__ uint_t dsm[];                              \
    uint_t dsm_u32 = (uint_t)__cvta_generic_to_shared(dsm);      \
    int tid = threadIdx.x, lane = tid & 31, wid = tid >> 5;      \
    int wm = (wid & 1) * 64, wn = (wid >> 1) * 32;               \
    ACC_INIT();

// K=32 chunk, bf16 3-term: ordered to minimize live fragment registers
__device__ __forceinline__ void mma_chunk32(uint_t sb, int wm, int wn, int lane,
                                            float acc[4][4][4]) {
    int l7 = lane & 7;
    int arow = ((lane >> 3) & 1) * 8 + l7;
    int aslot = lane >> 4;
    int brow = (lane >> 4) * 8 + l7;
    int bslot = (lane >> 3) & 1;
#pragma unroll
    for (int h = 0; h < 2; ++h) {
        uint_t ah[4][4], bh[4][2];
#pragma unroll
        for (int i = 0; i < 4; ++i)
            ldsm4r(ah[i], sb + SWZ((wm + i * 16 + arow) * 64 + h * 32 + aslot * 16));
#pragma unroll
        for (int jp = 0; jp < 2; ++jp) {
            uint_t r[4];
            ldsm4r(r, sb + 16384 + SWZ((wn + jp * 16 + brow) * 64 + h * 32 + bslot * 16));
            bh[2 * jp][0] = r[0]; bh[2 * jp][1] = r[1];
            bh[2 * jp + 1][0] = r[2]; bh[2 * jp + 1][1] = r[3];
        }
#pragma unroll
        for (int i = 0; i < 4; ++i)
#pragma unroll
            for (int j = 0; j < 4; ++j) mma_bf16(acc[i][j], ah[i], bh[j]);
        {
            uint_t bl[4][2];
#pragma unroll
            for (int jp = 0; jp < 2; ++jp) {
                uint_t r[4];
                ldsm4r(r, sb + 24576 + SWZ((wn + jp * 16 + brow) * 64 + h * 32 + bslot * 16));
                bl[2 * jp][0] = r[0]; bl[2 * jp][1] = r[1];
                bl[2 * jp + 1][0] = r[2]; bl[2 * jp + 1][1] = r[3];
            }
#pragma unroll
            for (int i = 0; i < 4; ++i)
#pragma unroll
                for (int j = 0; j < 4; ++j) mma_bf16(acc[i][j], ah[i], bl[j]);
        }
        {
            uint_t al[4][4];
#pragma unroll
            for (int i = 0; i < 4; ++i)
                ldsm4r(al[i], sb + 8192 + SWZ((wm + i * 16 + arow) * 64 + h * 32 + aslot * 16));
#pragma unroll
            for (int i = 0; i < 4; ++i)
#pragma unroll
                for (int j = 0; j < 4; ++j) mma_bf16(acc[i][j], al[i], bh[j]);
        }
    }
}

// K=32 chunk, fp16 2-term (conv): hh + lh, B_lo dropped
__device__ __forceinline__ void mma_chunk32_h(uint_t sb, int wm, int wn, int lane,
                                              float acc[4][4][4]) {
    int l7 = lane & 7;
    int arow = ((lane >> 3) & 1) * 8 + l7;
    int aslot = lane >> 4;
    int brow = (lane >> 4) * 8 + l7;
    int bslot = (lane >> 3) & 1;
#pragma unroll
    for (int h = 0; h < 2; ++h) {
        uint_t ah[4][4], bh[4][2];
#pragma unroll
        for (int i = 0; i < 4; ++i)
            ldsm4r(ah[i], sb + SWZ((wm + i * 16 + arow) * 64 + h * 32 + aslot * 16));
#pragma unroll
        for (int jp = 0; jp < 2; ++jp) {
            uint_t r[4];
            ldsm4r(r, sb + 16384 + SWZ((wn + jp * 16 + brow) * 64 + h * 32 + bslot * 16));
            bh[2 * jp][0] = r[0]; bh[2 * jp][1] = r[1];
            bh[2 * jp + 1][0] = r[2]; bh[2 * jp + 1][1] = r[3];
        }
#pragma unroll
        for (int i = 0; i < 4; ++i)
#pragma unroll
            for (int j = 0; j < 4; ++j) mma_f16(acc[i][j], ah[i], bh[j]);
        {
            uint_t al[4][4];
#pragma unroll
            for (int i = 0; i < 4; ++i)
                ldsm4r(al[i], sb + 8192 + SWZ((wm + i * 16 + arow) * 64 + h * 32 + aslot * 16));
#pragma unroll
            for (int i = 0; i < 4; ++i)
#pragma unroll
                for (int j = 0; j < 4; ++j) mma_f16(acc[i][j], al[i], bh[j]);
        }
    }
}

// 3-stage ring, lookahead 1 (NBUF=3 >= L+2): one barrier per 32-wide K chunk
#define PIPE3(NC, STRIDE, CHUNK)                                   \
    issue(0);                                                      \
    for (int c = 0; c < (NC); ++c) {                               \
        issue(c + 1);                                              \
        CP_WAIT1();                                                \
        __syncthreads();                                           \
        CHUNK(dsm_u32 + (c % 3) * (STRIDE), wm, wn, lane, acc);    \
    }

// ================= prepass kernels =================
__global__ void wnorm_scale_kernel(const float* __restrict__ v, const float* __restrict__ g) {
    int co = blockIdx.x;
    const float* vp = v + (size_t)co * (CIN * KW);
    float s = 0.f;
    for (int i = threadIdx.x; i < CIN * KW; i += blockDim.x) {
        float t = vp[i];
        s += t * t;
    }
    __shared__ float red[256];
    red[threadIdx.x] = s;
    __syncthreads();
    for (int o = 128; o > 0; o >>= 1) {
        if (threadIdx.x < o) red[threadIdx.x] += red[threadIdx.x + o];
        __syncthreads();
    }
    if (threadIdx.x == 0) g_scale[co] = g[co] * rsqrtf(red[0]);
}

// conv A planes (fp16): wH[co][k'=t*256+ci/2]
__global__ void wsplitH_kernel(const float* __restrict__ v) {
    int co = blockIdx.x;
    float sc = g_scale[co];
    for (int kp = threadIdx.x; kp < 1280; kp += 256) {
        int t = kp >> 8, ci = (kp & 255) * 2;
        size_t s = (size_t)co * (CIN * KW) + (size_t)ci * KW + t;
        uint_t hi, lo;
        split2h(v[s] * sc, v[s + KW] * sc, hi, lo);
        wH_hi[(size_t)co * 1280 + kp] = hi;
        wH_lo[(size_t)co * 1280 + kp] = lo;
    }
}

// conv B plane (fp16 hi only): xH_hi[b][l][ci/2]
__global__ void tsplit_xh_kernel(const float* __restrict__ x) {
    __shared__ float tile[32][33];
    int l0 = blockIdx.x * 32, c0 = blockIdx.y * 32, b = blockIdx.z;
    int tx = threadIdx.x, ty0 = threadIdx.y;
#pragma unroll
    for (int i = 0; i < 32; i += 8)
        tile[ty0 + i][tx] = x[((size_t)b * CIN + c0 + ty0 + i) * Lr + l0 + tx];
    __syncthreads();
    int id = ty0 * 32 + tx;
#pragma unroll
    for (int rpt = 0; rpt < 2; ++rpt) {
        int item = id + 256 * rpt;
        int l = item >> 4, u = item & 15;
        xH_hi[((size_t)b * Lr + l0 + l) * 256 + c0 / 2 + u] =
            pack_h(tile[2 * u][l], tile[2 * u + 1][l]);
    }
}

// fc1 A planes (bf16, transposed from g_h)
__global__ void tsplit_h_kernel() {
    __shared__ float tile[32][33];
    int l0 = blockIdx.x * 32, c0 = blockIdx.y * 32, b = blockIdx.z;
    int tx = threadIdx.x, ty0 = threadIdx.y;
#pragma unroll
    for (int i = 0; i < 32; i += 8)
        tile[ty0 + i][tx] = g_h[((size_t)b * HALF + c0 + ty0 + i) * Lr + l0 + tx];
    __syncthreads();
    int id = ty0 * 32 + tx;
#pragma unroll
    for (int rpt = 0; rpt < 2; ++rpt) {
        int item = id + 256 * rpt;
        int l = item >> 4, u = item & 15;
        uint_t hi, lo;
        split2(tile[2 * u][l], tile[2 * u + 1][l], hi, lo);
        size_t o = ((size_t)b * Lr + l0 + l) * 256 + c0 / 2 + u;
        hT_hi[o] = hi;
        hT_lo[o] = lo;
    }
}

__device__ __forceinline__ void ksplit_body(const float* __restrict__ src,
                                            uint_t* __restrict__ dhi,
                                            uint_t* __restrict__ dlo) {
    int n = blockIdx.x, kp = threadIdx.x;
    float2 p = *(const float2*)&src[(size_t)n * DW + 2 * kp];
    uint_t hi, lo;
    split2(p.x, p.y, hi, lo);
    dhi[(size_t)n * 256 + kp] = hi;
    dlo[(size_t)n * 256 + kp] = lo;
}
__global__ void ksplit_w1_kernel(const float* __restrict__ w) { ksplit_body(w, w1_hi, w1_lo); }
__global__ void ksplit_w2_kernel(const float* __restrict__ w) { ksplit_body(w, w2_hi, w2_lo); }

__global__ void fTsplit_kernel(const float* __restrict__ img) {
    __shared__ float tile[32][33];
    int p0 = blockIdx.x * 32, d0 = blockIdx.y * 32, b = blockIdx.z;
    int tx = threadIdx.x, ty0 = threadIdx.y;
#pragma unroll
    for (int i = 0; i < 32; i += 8) {
        int p = p0 + tx;
        tile[ty0 + i][tx] = (p < HW) ? img[((size_t)b * DW + d0 + ty0 + i) * HW + p] : 0.f;
    }
    __syncthreads();
    int id = ty0 * 32 + tx;
#pragma unroll
    for (int rpt = 0; rpt < 2; ++rpt) {
        int item = id + 256 * rpt;
        int p = item >> 4, u = item & 15;
        uint_t hi, lo;
        split2(tile[2 * u][p], tile[2 * u + 1][p], hi, lo);
        size_t o = ((size_t)b * 256 + p0 + p) * 256 + d0 / 2 + u;
        fT_hi[o] = hi;
        fT_lo[o] = lo;
    }
}

__global__ void fCsplit_kernel(const float* __restrict__ img) {
    int a = blockIdx.x, b = blockIdx.y, kp = threadIdx.x;
    if (kp >= 104) return;
    int p = 2 * kp;
    float v0 = (p < HW) ? img[((size_t)b * DW + a) * HW + p] : 0.f;
    float v1 = (p + 1 < HW) ? img[((size_t)b * DW + a) * HW + p + 1] : 0.f;
    uint_t hi, lo;
    split2(v0, v1, hi, lo);
    size_t o = ((size_t)b * DW + a) * 104 + kp;
    fC_hi[o] = hi;
    fC_lo[o] = lo;
}

// ================= causal conv as 5 shifted GEMMs (fp16 2-term) ===============
__global__ void __launch_bounds__(256, 2) conv_kernel(const float* __restrict__ bias) {
    GEMM_PROLOG();
    int l0 = blockIdx.x * 128, co0 = blockIdx.y * 128, b = blockIdx.z;
    const int NC = 80;  // 5 taps * 16 k32-chunks

    auto issue = [&](int c) {
        if (c < NC) {
            uint_t sb = dsm_u32 + (c % 3) * CS_STRIDE;
            int t = c >> 4;
#pragma unroll
            for (int g = 0; g < 2; ++g) {
                int item = g * 256 + tid;
                int rw = item >> 2, gk = item & 3;
                uint_t d = SWZ(rw * 64 + gk * 16);
                size_t ao = (size_t)(co0 + rw) * 1280 + c * 16 + gk * 4;
                cpa16(sb + d, wH_hi + ao, 1);
                cpa16(sb + 8192 + d, wH_lo + ao, 1);
                int xr = l0 + rw + t - 4;
                int ok = xr >= 0;
                size_t bo = ((size_t)b * Lr + (ok ? xr : 0)) * 256 + (c & 15) * 16 + gk * 4;
                cpa16(sb + 16384 + d, xH_hi + bo, ok);
            }
        }
        CP_COMMIT();
    };

    PIPE3(NC, CS_STRIDE, mma_chunk32_h)

    int r = lane >> 2;
#pragma unroll
    for (int i = 0; i < 4; ++i) {
        int co = co0 + wm + i * 16 + r;
        float b0 = bias[co], b1 = bias[co + 8];
#pragma unroll
        for (int j = 0; j < 4; ++j) {
            int l = l0 + wn + j * 8 + (lane & 3) * 2;
            *(float2*)&g_y[((size_t)b * COUT + co) * Lr + l] =
                make_float2(acc[i][j][0] + b0, acc[i][j][1] + b0);
            *(float2*)&g_y[((size_t)b * COUT + co + 8) * Lr + l] =
                make_float2(acc[i][j][2] + b1, acc[i][j][3] + b1);
        }
    }
}

// ================= GLU =================
__global__ void glu_kernel() {
    size_t p = (size_t)blockIdx.x * 256 + threadIdx.x;
    size_t e = p * 2;
    int l = (int)(e & 1023);
    size_t rest = e >> 10;
    int c = (int)(rest & 511);
    int b = (int)(rest >> 9);
    float2 a = *(const float2*)&g_y[((size_t)b * COUT + c) * Lr + l];
    float2 g = *(const float2*)&g_y[((size_t)b * COUT + c + HALF) * Lr + l];
    float2 r;
    r.x = a.x * (1.f / (1.f + expf(-g.x)));
    r.y = a.y * (1.f / (1.f + expf(-g.y)));
    *(float2*)&g_h[e] = r;
}

// ================= fc1: q = h^T W1^T + b1 + we -> q planes =================
__global__ void __launch_bounds__(256, 2) fc1_kernel(const float* __restrict__ bias,
                                                     const float* __restrict__ we) {
    GEMM_PROLOG();
    int a0 = blockIdx.x * 128, m0 = blockIdx.y * 128;
    int b = m0 >> 10, l0 = m0 & 1023;
    const int NC = 16;

    auto issue = [&](int c) {
        if (c < NC) {
            uint_t sb = dsm_u32 + (c % 3) * GS_STRIDE;
#pragma unroll
            for (int g = 0; g < 2; ++g) {
                int item = g * 256 + tid;
                int rw = item >> 2, gk = item & 3;
                uint_t d = SWZ(rw * 64 + gk * 16);
                size_t ao = ((size_t)b * Lr + l0 + rw) * 256 + c * 16 + gk * 4;
                cpa16(sb + d, hT_hi + ao, 1);
                cpa16(sb + 8192 + d, hT_lo + ao, 1);
                size_t bo = (size_t)(a0 + rw) * 256 + c * 16 + gk * 4;
                cpa16(sb + 16384 + d, w1_hi + bo, 1);
                cpa16(sb + 24576 + d, w1_lo + bo, 1);
            }
        }
        CP_COMMIT();
    };

    PIPE3(NC, GS_STRIDE, mma_chunk32)

    int r = lane >> 2;
#pragma unroll
    for (int i = 0; i < 4; ++i) {
        int m = m0 + wm + i * 16 + r;
#pragma unroll
        for (int j = 0; j < 4; ++j) {
            int a = a0 + wn + j * 8 + (lane & 3) * 2;
            int ua = a >> 1;
            float2 bb = *(const float2*)&bias[a];
            float2 w0 = *(const float2*)&we[(size_t)m * DW + a];
            float2 w1v = *(const float2*)&we[(size_t)(m + 8) * DW + a];
            uint_t hi, lo;
            split2(acc[i][j][0] + bb.x + w0.x, acc[i][j][1] + bb.y + w0.y, hi, lo);
            qP_hi[(size_t)m * 256 + ua] = hi;
            qP_lo[(size_t)m * 256 + ua] = lo;
            split2(acc[i][j][2] + bb.x + w1v.x, acc[i][j][3] + bb.y + w1v.y, hi, lo);
            qP_hi[(size_t)(m + 8) * 256 + ua] = hi;
            qP_lo[(size_t)(m + 8) * 256 + ua] = lo;
        }
    }
}

// ================= score = q @ feat =================
__global__ void __launch_bounds__(256, 2) score_kernel() {
    GEMM_PROLOG();
    int p0 = blockIdx.x * 128, m0 = blockIdx.y * 128;
    int b = m0 >> 10;
    const int NC = 16;

    auto issue = [&](int c) {
        if (c < NC) {
            uint_t sb = dsm_u32 + (c % 3) * GS_STRIDE;
#pragma unroll
            for (int g = 0; g < 2; ++g) {
                int item = g * 256 + tid;
                int rw = item >> 2, gk = item & 3;
                uint_t d = SWZ(rw * 64 + gk * 16);
                size_t ao = (size_t)(m0 + rw) * 256 + c * 16 + gk * 4;
                cpa16(sb + d, qP_hi + ao, 1);
                cpa16(sb + 8192 + d, qP_lo + ao, 1);
                size_t bo = ((size_t)b * 256 + p0 + rw) * 256 + c * 16 + gk * 4;
                cpa16(sb + 16384 + d, fT_hi + bo, 1);
                cpa16(sb + 24576 + d, fT_lo + bo, 1);
            }
        }
        CP_COMMIT();
    };

    PIPE3(NC, GS_STRIDE, mma_chunk32)

    int r = lane >> 2;
#pragma unroll
    for (int i = 0; i < 4; ++i) {
        int m = m0 + wm + i * 16 + r;
#pragma unroll
        for (int j = 0; j < 4; ++j) {
            int p = p0 + wn + j * 8 + (lane & 3) * 2;
            if (p < HW) {
                *(float2*)&g_score[(size_t)m * HW + p] =
                    make_float2(acc[i][j][0], acc[i][j][1]);
                *(float2*)&g_score[(size_t)(m + 8) * HW + p] =
                    make_float2(acc[i][j][2], acc[i][j][3]);
            }
        }
    }
}

// ================= softmax over 196 (+ fused aP split) =================
__global__ void softmax_kernel(float* __restrict__ attn) {
    __shared__ float sv[8][200];
    int warp = (blockIdx.x * blockDim.x + threadIdx.x) >> 5;
    int wloc = (threadIdx.x >> 5);
    int lane = threadIdx.x & 31;
    if (warp >= Bn * Lr) return;
    const float* sp = g_score + (size_t)warp * HW;
    float v[7];
    float mx = -1e30f;
#pragma unroll
    for (int i = 0; i < 7; ++i) {
        int p = lane + 32 * i;
        v[i] = (p < HW) ? sp[p] : -1e30f;
        mx = fmaxf(mx, v[i]);
    }
#pragma unroll
    for (int o = 16; o > 0; o >>= 1) mx = fmaxf(mx, __shfl_xor_sync(0xffffffffu, mx, o));
    float sum = 0.f;
#pragma unroll
    for (int i = 0; i < 7; ++i) {
        int p = lane + 32 * i;
        v[i] = (p < HW) ? expf(v[i] - mx) : 0.f;
        sum += v[i];
    }
#pragma unroll
    for (int o = 16; o > 0; o >>= 1) sum += __shfl_xor_sync(0xffffffffu, sum, o);
    float inv = 1.f / sum;
#pragma unroll
    for (int i = 0; i < 7; ++i) {
        int p = lane + 32 * i;
        if (p < HW) {
            float r = v[i] * inv;
            attn[(size_t)warp * HW + p] = r;
            sv[wloc][p] = r;
        }
    }
    __syncwarp();
#pragma unroll
    for (int kq = 0; kq < 4; ++kq) {
        int kp = lane + 32 * kq;
        if (kp < 104) {
            int p = 2 * kp;
            float v0 = (p < HW) ? sv[wloc][p] : 0.f;
            float v1 = (p + 1 < HW) ? sv[wloc][p + 1] : 0.f;
            uint_t hi, lo;
            split2(v0, v1, hi, lo);
            aP_hi[(size_t)warp * 104 + kp] = hi;
            aP_lo[(size_t)warp * 104 + kp] = lo;
        }
    }
}

// ================= ctx = attn @ feat^T -> ctx planes =================
__global__ void __launch_bounds__(256, 2) ctx_kernel() {
    GEMM_PROLOG();
    int a0 = blockIdx.x * 128, m0 = blockIdx.y * 128;
    int b = m0 >> 10;
    const int NC = 7;  // ceil(208/32)

    auto issue = [&](int c) {
        if (c < NC) {
            uint_t sb = dsm_u32 + (c % 3) * GS_STRIDE;
#pragma unroll
            for (int g = 0; g < 2; ++g) {
                int item = g * 256 + tid;
                int rw = item >> 2, gk = item & 3;
                uint_t d = SWZ(rw * 64 + gk * 16);
                int kp = c * 16 + gk * 4;
                int ok = kp < 104;
                size_t ao = (size_t)(m0 + rw) * 104 + kp;
                cpa16(sb + d, aP_hi + (ok ? ao : 0), ok);
                cpa16(sb + 8192 + d, aP_lo + (ok ? ao : 0), ok);
                size_t bo = ((size_t)b * DW + a0 + rw) * 104 + kp;
                cpa16(sb + 16384 + d, fC_hi + (ok ? bo : 0), ok);
                cpa16(sb + 24576 + d, fC_lo + (ok ? bo : 0), ok);
            }
        }
        CP_COMMIT();
    };

    PIPE3(NC, GS_STRIDE, mma_chunk32)

    int r = lane >> 2;
#pragma unroll
    for (int i = 0; i < 4; ++i) {
        int m = m0 + wm + i * 16 + r;
#pragma unroll
        for (int j = 0; j < 4; ++j) {
            int a = a0 + wn + j * 8 + (lane & 3) * 2;
            int ua = a >> 1;
            uint_t hi, lo;
            split2(acc[i][j][0], acc[i][j][1], hi, lo);
            cP_hi[(size_t)m * 256 + ua] = hi;
            cP_lo[(size_t)m * 256 + ua] = lo;
            split2(acc[i][j][2], acc[i][j][3], hi, lo);
            cP_hi[(size_t)(m + 8) * 256 + ua] = hi;
            cP_lo[(size_t)(m + 8) * 256 + ua] = lo;
        }
    }
}

// ================= fc2 + residuals, transposed output =================
__global__ void __launch_bounds__(256, 2) fc2_kernel(const float* __restrict__ bias,
                                                     const float* __restrict__ x,
                                                     float* __restrict__ out) {
    GEMM_PROLOG();
    int l0 = blockIdx.x * 128, c0 = blockIdx.y * 128, b = blockIdx.z;
    const int NC = 16;

    auto issue = [&](int c) {
        if (c < NC) {
            uint_t sb = dsm_u32 + (c % 3) * GS_STRIDE;
#pragma unroll
            for (int g = 0; g < 2; ++g) {
                int item = g * 256 + tid;
                int rw = item >> 2, gk = item & 3;
                uint_t d = SWZ(rw * 64 + gk * 16);
                size_t ao = (size_t)(c0 + rw) * 256 + c * 16 + gk * 4;
                cpa16(sb + d, w2_hi + ao, 1);
                cpa16(sb + 8192 + d, w2_lo + ao, 1);
                size_t bo = ((size_t)b * Lr + l0 + rw) * 256 + c * 16 + gk * 4;
                cpa16(sb + 16384 + d, cP_hi + bo, 1);
                cpa16(sb + 24576 + d, cP_lo + bo, 1);
            }
        }
        CP_COMMIT();
    };

    PIPE3(NC, GS_STRIDE, mma_chunk32)

    int r = lane >> 2;
#pragma unroll
    for (int i = 0; i < 4; ++i) {
        int cc = c0 + wm + i * 16 + r;
        float b0 = bias[cc], b1 = bias[cc + 8];
#pragma unroll
        for (int j = 0; j < 4; ++j) {
            int l = l0 + wn + j * 8 + (lane & 3) * 2;
            size_t o0 = ((size_t)b * HALF + cc) * Lr + l;
            size_t o1 = ((size_t)b * HALF + cc + 8) * Lr + l;
            float2 h0 = *(const float2*)&g_h[o0];
            float2 x0 = *(const float2*)&x[o0];
            float2 h1 = *(const float2*)&g_h[o1];
            float2 x1 = *(const float2*)&x[o1];
            *(float2*)&out[o0] = make_float2(acc[i][j][0] + b0 + h0.x + x0.x,
                                             acc[i][j][1] + b0 + h0.y + x0.y);
            *(float2*)&out[o1] = make_float2(acc[i][j][2] + b1 + h1.x + x1.x,
                                             acc[i][j][3] + b1 + h1.y + x1.y);
        }
    }
}

// ================= launch =================
extern "C" void kernel_launch(void* const* d_in, const int* in_sizes, int n_in,
                              void* d_out, int out_size) {
    const float* x      = (const float*)d_in[0];
    const float* we     = (const float*)d_in[1];
    const float* img    = (const float*)d_in[2];
    const float* conv_v = (const float*)d_in[4];
    const float* conv_g = (const float*)d_in[5];
    const float* conv_b = (const float*)d_in[6];
    const float* fc1_w  = (const float*)d_in[7];
    const float* fc1_b  = (const float*)d_in[8];
    const float* fc2_w  = (const float*)d_in[9];
    const float* fc2_b  = (const float*)d_in[10];

    float* out = (float*)d_out;
    const size_t SZ_OUT = (size_t)Bn * HALF * Lr;
    const size_t SZ_WE  = (size_t)Bn * Lr * DW;
    const size_t SZ_IMG = (size_t)Bn * DW * HW;
    float* out_we   = out + SZ_OUT;
    float* out_img  = out_we + SZ_WE;
    float* out_attn = out_img + SZ_IMG;

    cudaFuncSetAttribute(conv_kernel, cudaFuncAttributeMaxDynamicSharedMemorySize, DSMEM_C);
    cudaFuncSetAttribute(fc1_kernel, cudaFuncAttributeMaxDynamicSharedMemorySize, DSMEM_G);
    cudaFuncSetAttribute(score_kernel, cudaFuncAttributeMaxDynamicSharedMemorySize, DSMEM_G);
    cudaFuncSetAttribute(ctx_kernel, cudaFuncAttributeMaxDynamicSharedMemorySize, DSMEM_G);
    cudaFuncSetAttribute(fc2_kernel, cudaFuncAttributeMaxDynamicSharedMemorySize, DSMEM_G);

    // prepass splits
    wnorm_scale_kernel<<<COUT, 256>>>(conv_v, conv_g);
    wsplitH_kernel<<<COUT, 256>>>(conv_v);
    tsplit_xh_kernel<<<dim3(Lr / 32, CIN / 32, Bn), dim3(32, 8)>>>(x);
    ksplit_w1_kernel<<<DW, 256>>>(fc1_w);
    ksplit_w2_kernel<<<HALF, 256>>>(fc2_w);
    fTsplit_kernel<<<dim3(8, DW / 32, Bn), dim3(32, 8)>>>(img);
    fCsplit_kernel<<<dim3(DW, Bn), 128>>>(img);

    conv_kernel<<<dim3(Lr / 128, COUT / 128, Bn), 256, DSMEM_C>>>(conv_b);
    glu_kernel<<<(Bn * HALF * Lr) / 512, 256>>>();
    tsplit_h_kernel<<<dim3(Lr / 32, HALF / 32, Bn), dim3(32, 8)>>>();
    fc1_kernel<<<dim3(DW / 128, (Bn * Lr) / 128), 256, DSMEM_G>>>(fc1_b, we);
    score_kernel<<<dim3(2, (Bn * Lr) / 128), 256, DSMEM_G>>>();
    softmax_kernel<<<(Bn * Lr) / 8, 256>>>(out_attn);
    ctx_kernel<<<dim3(DW / 128, (Bn * Lr) / 128), 256, DSMEM_G>>>();
    fc2_kernel<<<dim3(Lr / 128, HALF / 128, Bn), 256, DSMEM_G>>>(fc2_b, x, out);

    cudaMemcpyAsync(out_we, we, SZ_WE * sizeof(float), cudaMemcpyDeviceToDevice, 0);
    cudaMemcpyAsync(out_img, img, SZ_IMG * sizeof(float), cudaMemcpyDeviceToDevice, 0);
}

// round 16
// speedup vs baseline: 2.7000x; 1.0622x over previous
#include <cuda_runtime.h>
#include <math.h>

#define Bn   16
#define CIN  512
#define Lr   1024
#define COUT 1024
#define KW   5
#define DW   512
#define HW   196
#define HALF 512

typedef unsigned uint_t;

// ---- scratch (device globals; no allocation allowed) ----
__device__ float g_y[(size_t)Bn * COUT * Lr];      // conv output (pre-GLU)
__device__ float g_h[(size_t)Bn * HALF * Lr];      // GLU output (fp32, fc2 residual)
__device__ float g_score[(size_t)Bn * Lr * HW];

// conv planes: fp16 (2-term split, no B_lo plane)
__device__ __align__(16) uint_t wH_hi[COUT * 1280], wH_lo[COUT * 1280];          // A [co][k'=t*256+ci/2]
__device__ __align__(16) uint_t xH_hi[(size_t)Bn * Lr * 256];                    // B [b][l][ci/2]
// bf16 hi/lo planes (fc1 / score — precision-critical path)
__device__ __align__(16) uint_t hT_hi[(size_t)Bn * Lr * 256], hT_lo[(size_t)Bn * Lr * 256];   // fc1 A [b][l][c/2]
__device__ __align__(16) uint_t w1_hi[DW * 256], w1_lo[DW * 256];                // fc1 B [a][c/2]
__device__ __align__(16) uint_t qP_hi[(size_t)Bn * Lr * 256], qP_lo[(size_t)Bn * Lr * 256];   // score A [m][a/2]
__device__ __align__(16) uint_t fT_hi[(size_t)Bn * 256 * 256], fT_lo[(size_t)Bn * 256 * 256]; // score B [b][p pad256][dw/2]
// fp16 planes (ctx / fc2 — post-softmax path)
__device__ __align__(16) uint_t aP_hi[(size_t)Bn * Lr * 104], aP_lo[(size_t)Bn * Lr * 104];   // ctx A [m][p/2 pad104]
__device__ __align__(16) uint_t fC_hi[(size_t)Bn * DW * 104];                    // ctx B [b][a][p/2]
__device__ __align__(16) uint_t cP_hi[(size_t)Bn * Lr * 256];                    // fc2 B [m][a/2]
__device__ __align__(16) uint_t w2_hi[HALF * 256], w2_lo[HALF * 256];            // fc2 A [c][a/2]

// ---- split helpers ----
__device__ __forceinline__ void split2(float v0, float v1, uint_t& hi, uint_t& lo) {  // bf16
    asm("cvt.rn.bf16x2.f32 %0, %1, %2;" : "=r"(hi) : "f"(v1), "f"(v0));
    float h0 = __uint_as_float(hi << 16);
    float h1 = __uint_as_float(hi & 0xffff0000u);
    asm("cvt.rn.bf16x2.f32 %0, %1, %2;" : "=r"(lo) : "f"(v1 - h1), "f"(v0 - h0));
}
__device__ __forceinline__ void split2h(float v0, float v1, uint_t& hi, uint_t& lo) {  // fp16
    asm("cvt.rn.f16x2.f32 %0, %1, %2;" : "=r"(hi) : "f"(v1), "f"(v0));
    float h0, h1;
    asm("{\n\t.reg .b16 a,b;\n\tmov.b32 {a,b}, %2;\n\tcvt.f32.f16 %0, a;\n\tcvt.f32.f16 %1, b;\n\t}"
        : "=f"(h0), "=f"(h1) : "r"(hi));
    asm("cvt.rn.f16x2.f32 %0, %1, %2;" : "=r"(lo) : "f"(v1 - h1), "f"(v0 - h0));
}
__device__ __forceinline__ uint_t pack_h(float v0, float v1) {
    uint_t r;
    asm("cvt.rn.f16x2.f32 %0, %1, %2;" : "=r"(r) : "f"(v1), "f"(v0));
    return r;
}

__device__ __forceinline__ void mma_bf16(float* c, const uint_t* a, const uint_t* b) {
    asm volatile(
        "mma.sync.aligned.m16n8k16.row.col.f32.bf16.bf16.f32 "
        "{%0,%1,%2,%3}, {%4,%5,%6,%7}, {%8,%9}, {%0,%1,%2,%3};"
        : "+f"(c[0]), "+f"(c[1]), "+f"(c[2]), "+f"(c[3])
        : "r"(a[0]), "r"(a[1]), "r"(a[2]), "r"(a[3]), "r"(b[0]), "r"(b[1]));
}
__device__ __forceinline__ void mma_f16(float* c, const uint_t* a, const uint_t* b) {
    asm volatile(
        "mma.sync.aligned.m16n8k16.row.col.f32.f16.f16.f32 "
        "{%0,%1,%2,%3}, {%4,%5,%6,%7}, {%8,%9}, {%0,%1,%2,%3};"
        : "+f"(c[0]), "+f"(c[1]), "+f"(c[2]), "+f"(c[3])
        : "r"(a[0]), "r"(a[1]), "r"(a[2]), "r"(a[3]), "r"(b[0]), "r"(b[1]));
}

__device__ __forceinline__ void ldsm4r(uint_t* r, uint_t addr) {
    asm volatile("ldmatrix.sync.aligned.m8n8.x4.shared.b16 {%0,%1,%2,%3}, [%4];"
                 : "=r"(r[0]), "=r"(r[1]), "=r"(r[2]), "=r"(r[3]) : "r"(addr));
}

__device__ __forceinline__ void cpa16(uint_t sdst, const void* g, int ok) {
    asm volatile("cp.async.cg.shared.global [%0], [%1], 16, %2;"
                 :: "r"(sdst), "l"(g), "r"(ok ? 16 : 0) : "memory");
}
#define CP_COMMIT() asm volatile("cp.async.commit_group;" ::: "memory")

#define SWZ(o) ((o) ^ (((o) >> 3) & 0x70))

// bf16 4-plane stage (fc1/score): planes 0/8192/16384/24576, stride 32KB, 3-stage ring
#define GS_STRIDE 32768
#define DSMEM_G  (3 * GS_STRIDE)
// fp16 3-plane stage (conv/ctx/fc2): A_hi 0, A_lo 8192, B_hi 16384, stride 24KB, 4-stage ring
#define CS_STRIDE 24576
#define DSMEM_C  (4 * CS_STRIDE)

#define ACC_INIT()                                    \
    float acc[4][4][4];                               \
    _Pragma("unroll") for (int i = 0; i < 4; ++i)     \
        _Pragma("unroll") for (int j = 0; j < 4; ++j) \
            _Pragma("unroll") for (int t = 0; t < 4; ++t) acc[i][j][t] = 0.f;

#define GEMM_PROLOG()                                            \
    extern __shared__ uint_t dsm[];                              \
    uint_t dsm_u32 = (uint_t)__cvta_generic_to_shared(dsm);      \
    int tid = threadIdx.x, lane = tid & 31, wid = tid >> 5;      \
    int wm = (wid & 1) * 64, wn = (wid >> 1) * 32;               \
    ACC_INIT();

// K=32 chunk, bf16 3-term
__device__ __forceinline__ void mma_chunk32(uint_t sb, int wm, int wn, int lane,
                                            float acc[4][4][4]) {
    int l7 = lane & 7;
    int arow = ((lane >> 3) & 1) * 8 + l7;
    int aslot = lane >> 4;
    int brow = (lane >> 4) * 8 + l7;
    int bslot = (lane >> 3) & 1;
#pragma unroll
    for (int h = 0; h < 2; ++h) {
        uint_t ah[4][4], bh[4][2];
#pragma unroll
        for (int i = 0; i < 4; ++i)
            ldsm4r(ah[i], sb + SWZ((wm + i * 16 + arow) * 64 + h * 32 + aslot * 16));
#pragma unroll
        for (int jp = 0; jp < 2; ++jp) {
            uint_t r[4];
            ldsm4r(r, sb + 16384 + SWZ((wn + jp * 16 + brow) * 64 + h * 32 + bslot * 16));
            bh[2 * jp][0] = r[0]; bh[2 * jp][1] = r[1];
            bh[2 * jp + 1][0] = r[2]; bh[2 * jp + 1][1] = r[3];
        }
#pragma unroll
        for (int i = 0; i < 4; ++i)
#pragma unroll
            for (int j = 0; j < 4; ++j) mma_bf16(acc[i][j], ah[i], bh[j]);
        {
            uint_t bl[4][2];
#pragma unroll
            for (int jp = 0; jp < 2; ++jp) {
                uint_t r[4];
                ldsm4r(r, sb + 24576 + SWZ((wn + jp * 16 + brow) * 64 + h * 32 + bslot * 16));
                bl[2 * jp][0] = r[0]; bl[2 * jp][1] = r[1];
                bl[2 * jp + 1][0] = r[2]; bl[2 * jp + 1][1] = r[3];
            }
#pragma unroll
            for (int i = 0; i < 4; ++i)
#pragma unroll
                for (int j = 0; j < 4; ++j) mma_bf16(acc[i][j], ah[i], bl[j]);
        }
        {
            uint_t al[4][4];
#pragma unroll
            for (int i = 0; i < 4; ++i)
                ldsm4r(al[i], sb + 8192 + SWZ((wm + i * 16 + arow) * 64 + h * 32 + aslot * 16));
#pragma unroll
            for (int i = 0; i < 4; ++i)
#pragma unroll
                for (int j = 0; j < 4; ++j) mma_bf16(acc[i][j], al[i], bh[j]);
        }
    }
}

// K=32 chunk, fp16 2-term (conv/ctx/fc2): hh + lh
__device__ __forceinline__ void mma_chunk32_h(uint_t sb, int wm, int wn, int lane,
                                              float acc[4][4][4]) {
    int l7 = lane & 7;
    int arow = ((lane >> 3) & 1) * 8 + l7;
    int aslot = lane >> 4;
    int brow = (lane >> 4) * 8 + l7;
    int bslot = (lane >> 3) & 1;
#pragma unroll
    for (int h = 0; h < 2; ++h) {
        uint_t ah[4][4], bh[4][2];
#pragma unroll
        for (int i = 0; i < 4; ++i)
            ldsm4r(ah[i], sb + SWZ((wm + i * 16 + arow) * 64 + h * 32 + aslot * 16));
#pragma unroll
        for (int jp = 0; jp < 2; ++jp) {
            uint_t r[4];
            ldsm4r(r, sb + 16384 + SWZ((wn + jp * 16 + brow) * 64 + h * 32 + bslot * 16));
            bh[2 * jp][0] = r[0]; bh[2 * jp][1] = r[1];
            bh[2 * jp + 1][0] = r[2]; bh[2 * jp + 1][1] = r[3];
        }
#pragma unroll
        for (int i = 0; i < 4; ++i)
#pragma unroll
            for (int j = 0; j < 4; ++j) mma_f16(acc[i][j], ah[i], bh[j]);
        {
            uint_t al[4][4];
#pragma unroll
            for (int i = 0; i < 4; ++i)
                ldsm4r(al[i], sb + 8192 + SWZ((wm + i * 16 + arow) * 64 + h * 32 + aslot * 16));
#pragma unroll
            for (int i = 0; i < 4; ++i)
#pragma unroll
                for (int j = 0; j < 4; ++j) mma_f16(acc[i][j], al[i], bh[j]);
        }
    }
}

// 3-stage ring, lookahead 1 (bf16 kernels)
#define PIPE3(NC, STRIDE, CHUNK)                                   \
    issue(0);                                                      \
    for (int c = 0; c < (NC); ++c) {                               \
        issue(c + 1);                                              \
        asm volatile("cp.async.wait_group 1;" ::: "memory");       \
        __syncthreads();                                           \
        CHUNK(dsm_u32 + (c % 3) * (STRIDE), wm, wn, lane, acc);    \
    }

// 4-stage ring, lookahead 2 (fp16 kernels): buffer (c+2)&3 reuse is protected by
// iteration c-1's barrier (which follows mma(c-2) in program order)
#define PIPE4(NC, STRIDE, CHUNK)                                   \
    issue(0); issue(1);                                            \
    for (int c = 0; c < (NC); ++c) {                               \
        issue(c + 2);                                              \
        asm volatile("cp.async.wait_group 2;" ::: "memory");       \
        __syncthreads();                                           \
        CHUNK(dsm_u32 + (c & 3) * (STRIDE), wm, wn, lane, acc);    \
    }

// ================= prepass kernels =================
// fused weight-norm + fp16 split (v cached in smem; one launch, one v read)
__global__ void wsplit_fused_kernel(const float* __restrict__ v, const float* __restrict__ g) {
    __shared__ float vbuf[CIN * KW];
    __shared__ float red[256];
    int co = blockIdx.x, tid = threadIdx.x;
    const float* vp = v + (size_t)co * (CIN * KW);
    float s = 0.f;
    for (int i = tid; i < CIN * KW; i += 256) {
        float t = vp[i];
        vbuf[i] = t;
        s += t * t;
    }
    red[tid] = s;
    __syncthreads();
    for (int o = 128; o > 0; o >>= 1) {
        if (tid < o) red[tid] += red[tid + o];
        __syncthreads();
    }
    float sc = g[co] * rsqrtf(red[0]);
    for (int kp = tid; kp < 1280; kp += 256) {
        int t = kp >> 8, ci = (kp & 255) * 2;
        int si = ci * KW + t;
        uint_t hi, lo;
        split2h(vbuf[si] * sc, vbuf[si + KW] * sc, hi, lo);
        wH_hi[(size_t)co * 1280 + kp] = hi;
        wH_lo[(size_t)co * 1280 + kp] = lo;
    }
}

// conv B plane (fp16 hi only): xH_hi[b][l][ci/2]
__global__ void tsplit_xh_kernel(const float* __restrict__ x) {
    __shared__ float tile[32][33];
    int l0 = blockIdx.x * 32, c0 = blockIdx.y * 32, b = blockIdx.z;
    int tx = threadIdx.x, ty0 = threadIdx.y;
#pragma unroll
    for (int i = 0; i < 32; i += 8)
        tile[ty0 + i][tx] = x[((size_t)b * CIN + c0 + ty0 + i) * Lr + l0 + tx];
    __syncthreads();
    int id = ty0 * 32 + tx;
#pragma unroll
    for (int rpt = 0; rpt < 2; ++rpt) {
        int item = id + 256 * rpt;
        int l = item >> 4, u = item & 15;
        xH_hi[((size_t)b * Lr + l0 + l) * 256 + c0 / 2 + u] =
            pack_h(tile[2 * u][l], tile[2 * u + 1][l]);
    }
}

// fused GLU + transpose-split: reads g_y pairs, writes g_h AND hT planes
__global__ void glu_tsplit_kernel() {
    __shared__ float tile[32][33];
    int l0 = blockIdx.x * 32, c0 = blockIdx.y * 32, b = blockIdx.z;
    int tx = threadIdx.x, ty0 = threadIdx.y;
#pragma unroll
    for (int i = 0; i < 32; i += 8) {
        int c = c0 + ty0 + i;
        float a = g_y[((size_t)b * COUT + c) * Lr + l0 + tx];
        float gv = g_y[((size_t)b * COUT + c + HALF) * Lr + l0 + tx];
        float h = a * (1.f / (1.f + expf(-gv)));
        tile[ty0 + i][tx] = h;
        g_h[((size_t)b * HALF + c) * Lr + l0 + tx] = h;
    }
    __syncthreads();
    int id = ty0 * 32 + tx;
#pragma unroll
    for (int rpt = 0; rpt < 2; ++rpt) {
        int item = id + 256 * rpt;
        int l = item >> 4, u = item & 15;
        uint_t hi, lo;
        split2(tile[2 * u][l], tile[2 * u + 1][l], hi, lo);
        size_t o = ((size_t)b * Lr + l0 + l) * 256 + c0 / 2 + u;
        hT_hi[o] = hi;
        hT_lo[o] = lo;
    }
}

__global__ void ksplit_w1_kernel(const float* __restrict__ w) {  // bf16 hi/lo
    int n = blockIdx.x, kp = threadIdx.x;
    float2 p = *(const float2*)&w[(size_t)n * DW + 2 * kp];
    uint_t hi, lo;
    split2(p.x, p.y, hi, lo);
    w1_hi[(size_t)n * 256 + kp] = hi;
    w1_lo[(size_t)n * 256 + kp] = lo;
}
__global__ void ksplit_w2_kernel(const float* __restrict__ w) {  // fp16 hi/lo
    int n = blockIdx.x, kp = threadIdx.x;
    float2 p = *(const float2*)&w[(size_t)n * DW + 2 * kp];
    uint_t hi, lo;
    split2h(p.x, p.y, hi, lo);
    w2_hi[(size_t)n * 256 + kp] = hi;
    w2_lo[(size_t)n * 256 + kp] = lo;
}

__global__ void fTsplit_kernel(const float* __restrict__ img) {  // bf16 hi/lo
    __shared__ float tile[32][33];
    int p0 = blockIdx.x * 32, d0 = blockIdx.y * 32, b = blockIdx.z;
    int tx = threadIdx.x, ty0 = threadIdx.y;
#pragma unroll
    for (int i = 0; i < 32; i += 8) {
        int p = p0 + tx;
        tile[ty0 + i][tx] = (p < HW) ? img[((size_t)b * DW + d0 + ty0 + i) * HW + p] : 0.f;
    }
    __syncthreads();
    int id = ty0 * 32 + tx;
#pragma unroll
    for (int rpt = 0; rpt < 2; ++rpt) {
        int item = id + 256 * rpt;
        int p = item >> 4, u = item & 15;
        uint_t hi, lo;
        split2(tile[2 * u][p], tile[2 * u + 1][p], hi, lo);
        size_t o = ((size_t)b * 256 + p0 + p) * 256 + d0 / 2 + u;
        fT_hi[o] = hi;
        fT_lo[o] = lo;
    }
}

__global__ void fCsplit_kernel(const float* __restrict__ img) {  // fp16 hi only
    int a = blockIdx.x, b = blockIdx.y, kp = threadIdx.x;
    if (kp >= 104) return;
    int p = 2 * kp;
    float v0 = (p < HW) ? img[((size_t)b * DW + a) * HW + p] : 0.f;
    float v1 = (p + 1 < HW) ? img[((size_t)b * DW + a) * HW + p + 1] : 0.f;
    fC_hi[((size_t)b * DW + a) * 104 + kp] = pack_h(v0, v1);
}

// ================= causal conv as 5 shifted GEMMs (fp16 2-term) ===============
__global__ void __launch_bounds__(256, 2) conv_kernel(const float* __restrict__ bias) {
    GEMM_PROLOG();
    int l0 = blockIdx.x * 128, co0 = blockIdx.y * 128, b = blockIdx.z;
    const int NC = 80;  // 5 taps * 16 k32-chunks

    auto issue = [&](int c) {
        if (c < NC) {
            uint_t sb = dsm_u32 + (c & 3) * CS_STRIDE;
            int t = c >> 4;
#pragma unroll
            for (int g = 0; g < 2; ++g) {
                int item = g * 256 + tid;
                int rw = item >> 2, gk = item & 3;
                uint_t d = SWZ(rw * 64 + gk * 16);
                size_t ao = (size_t)(co0 + rw) * 1280 + c * 16 + gk * 4;
                cpa16(sb + d, wH_hi + ao, 1);
                cpa16(sb + 8192 + d, wH_lo + ao, 1);
                int xr = l0 + rw + t - 4;
                int ok = xr >= 0;
                size_t bo = ((size_t)b * Lr + (ok ? xr : 0)) * 256 + (c & 15) * 16 + gk * 4;
                cpa16(sb + 16384 + d, xH_hi + bo, ok);
            }
        }
        CP_COMMIT();
    };

    PIPE4(NC, CS_STRIDE, mma_chunk32_h)

    int r = lane >> 2;
#pragma unroll
    for (int i = 0; i < 4; ++i) {
        int co = co0 + wm + i * 16 + r;
        float b0 = bias[co], b1 = bias[co + 8];
#pragma unroll
        for (int j = 0; j < 4; ++j) {
            int l = l0 + wn + j * 8 + (lane & 3) * 2;
            *(float2*)&g_y[((size_t)b * COUT + co) * Lr + l] =
                make_float2(acc[i][j][0] + b0, acc[i][j][1] + b0);
            *(float2*)&g_y[((size_t)b * COUT + co + 8) * Lr + l] =
                make_float2(acc[i][j][2] + b1, acc[i][j][3] + b1);
        }
    }
}

// ================= fc1: q = h^T W1^T + b1 + we -> q planes (bf16x3) ===========
__global__ void __launch_bounds__(256, 2) fc1_kernel(const float* __restrict__ bias,
                                                     const float* __restrict__ we) {
    GEMM_PROLOG();
    int a0 = blockIdx.x * 128, m0 = blockIdx.y * 128;
    int b = m0 >> 10, l0 = m0 & 1023;
    const int NC = 16;

    auto issue = [&](int c) {
        if (c < NC) {
            uint_t sb = dsm_u32 + (c % 3) * GS_STRIDE;
#pragma unroll
            for (int g = 0; g < 2; ++g) {
                int item = g * 256 + tid;
                int rw = item >> 2, gk = item & 3;
                uint_t d = SWZ(rw * 64 + gk * 16);
                size_t ao = ((size_t)b * Lr + l0 + rw) * 256 + c * 16 + gk * 4;
                cpa16(sb + d, hT_hi + ao, 1);
                cpa16(sb + 8192 + d, hT_lo + ao, 1);
                size_t bo = (size_t)(a0 + rw) * 256 + c * 16 + gk * 4;
                cpa16(sb + 16384 + d, w1_hi + bo, 1);
                cpa16(sb + 24576 + d, w1_lo + bo, 1);
            }
        }
        CP_COMMIT();
    };

    PIPE3(NC, GS_STRIDE, mma_chunk32)

    int r = lane >> 2;
#pragma unroll
    for (int i = 0; i < 4; ++i) {
        int m = m0 + wm + i * 16 + r;
#pragma unroll
        for (int j = 0; j < 4; ++j) {
            int a = a0 + wn + j * 8 + (lane & 3) * 2;
            int ua = a >> 1;
            float2 bb = *(const float2*)&bias[a];
            float2 w0 = *(const float2*)&we[(size_t)m * DW + a];
            float2 w1v = *(const float2*)&we[(size_t)(m + 8) * DW + a];
            uint_t hi, lo;
            split2(acc[i][j][0] + bb.x + w0.x, acc[i][j][1] + bb.y + w0.y, hi, lo);
            qP_hi[(size_t)m * 256 + ua] = hi;
            qP_lo[(size_t)m * 256 + ua] = lo;
            split2(acc[i][j][2] + bb.x + w1v.x, acc[i][j][3] + bb.y + w1v.y, hi, lo);
            qP_hi[(size_t)(m + 8) * 256 + ua] = hi;
            qP_lo[(size_t)(m + 8) * 256 + ua] = lo;
        }
    }
}

// ================= score = q @ feat (bf16x3) =================
__global__ void __launch_bounds__(256, 2) score_kernel() {
    GEMM_PROLOG();
    int p0 = blockIdx.x * 128, m0 = blockIdx.y * 128;
    int b = m0 >> 10;
    const int NC = 16;

    auto issue = [&](int c) {
        if (c < NC) {
            uint_t sb = dsm_u32 + (c % 3) * GS_STRIDE;
#pragma unroll
            for (int g = 0; g < 2; ++g) {
                int item = g * 256 + tid;
                int rw = item >> 2, gk = item & 3;
                uint_t d = SWZ(rw * 64 + gk * 16);
                size_t ao = (size_t)(m0 + rw) * 256 + c * 16 + gk * 4;
                cpa16(sb + d, qP_hi + ao, 1);
                cpa16(sb + 8192 + d, qP_lo + ao, 1);
                size_t bo = ((size_t)b * 256 + p0 + rw) * 256 + c * 16 + gk * 4;
                cpa16(sb + 16384 + d, fT_hi + bo, 1);
                cpa16(sb + 24576 + d, fT_lo + bo, 1);
            }
        }
        CP_COMMIT();
    };

    PIPE3(NC, GS_STRIDE, mma_chunk32)

    int r = lane >> 2;
#pragma unroll
    for (int i = 0; i < 4; ++i) {
        int m = m0 + wm + i * 16 + r;
#pragma unroll
        for (int j = 0; j < 4; ++j) {
            int p = p0 + wn + j * 8 + (lane & 3) * 2;
            if (p < HW) {
                *(float2*)&g_score[(size_t)m * HW + p] =
                    make_float2(acc[i][j][0], acc[i][j][1]);
                *(float2*)&g_score[(size_t)(m + 8) * HW + p] =
                    make_float2(acc[i][j][2], acc[i][j][3]);
            }
        }
    }
}

// ================= softmax over 196 (+ fused fp16 aP split) =================
__global__ void softmax_kernel(float* __restrict__ attn) {
    __shared__ float sv[8][200];
    int warp = (blockIdx.x * blockDim.x + threadIdx.x) >> 5;
    int wloc = (threadIdx.x >> 5);
    int lane = threadIdx.x & 31;
    if (warp >= Bn * Lr) return;
    const float* sp = g_score + (size_t)warp * HW;
    float v[7];
    float mx = -1e30f;
#pragma unroll
    for (int i = 0; i < 7; ++i) {
        int p = lane + 32 * i;
        v[i] = (p < HW) ? sp[p] : -1e30f;
        mx = fmaxf(mx, v[i]);
    }
#pragma unroll
    for (int o = 16; o > 0; o >>= 1) mx = fmaxf(mx, __shfl_xor_sync(0xffffffffu, mx, o));
    float sum = 0.f;
#pragma unroll
    for (int i = 0; i < 7; ++i) {
        int p = lane + 32 * i;
        v[i] = (p < HW) ? expf(v[i] - mx) : 0.f;
        sum += v[i];
    }
#pragma unroll
    for (int o = 16; o > 0; o >>= 1) sum += __shfl_xor_sync(0xffffffffu, sum, o);
    float inv = 1.f / sum;
#pragma unroll
    for (int i = 0; i < 7; ++i) {
        int p = lane + 32 * i;
        if (p < HW) {
            float r = v[i] * inv;
            attn[(size_t)warp * HW + p] = r;
            sv[wloc][p] = r;
        }
    }
    __syncwarp();
#pragma unroll
    for (int kq = 0; kq < 4; ++kq) {
        int kp = lane + 32 * kq;
        if (kp < 104) {
            int p = 2 * kp;
            float v0 = (p < HW) ? sv[wloc][p] : 0.f;
            float v1 = (p + 1 < HW) ? sv[wloc][p + 1] : 0.f;
            uint_t hi, lo;
            split2h(v0, v1, hi, lo);
            aP_hi[(size_t)warp * 104 + kp] = hi;
            aP_lo[(size_t)warp * 104 + kp] = lo;
        }
    }
}

// ================= ctx = attn @ feat^T (fp16 2-term) -> cP hi plane ===========
__global__ void __launch_bounds__(256, 2) ctx_kernel() {
    GEMM_PROLOG();
    int a0 = blockIdx.x * 128, m0 = blockIdx.y * 128;
    int b = m0 >> 10;
    const int NC = 7;  // ceil(208/32)

    auto issue = [&](int c) {
        if (c < NC) {
            uint_t sb = dsm_u32 + (c & 3) * CS_STRIDE;
#pragma unroll
            for (int g = 0; g < 2; ++g) {
                int item = g * 256 + tid;
                int rw = item >> 2, gk = item & 3;
                uint_t d = SWZ(rw * 64 + gk * 16);
                int kp = c * 16 + gk * 4;
                int ok = kp < 104;
                size_t ao = (size_t)(m0 + rw) * 104 + kp;
                cpa16(sb + d, aP_hi + (ok ? ao : 0), ok);
                cpa16(sb + 8192 + d, aP_lo + (ok ? ao : 0), ok);
                size_t bo = ((size_t)b * DW + a0 + rw) * 104 + kp;
                cpa16(sb + 16384 + d, fC_hi + (ok ? bo : 0), ok);
            }
        }
        CP_COMMIT();
    };

    PIPE4(NC, CS_STRIDE, mma_chunk32_h)

    int r = lane >> 2;
#pragma unroll
    for (int i = 0; i < 4; ++i) {
        int m = m0 + wm + i * 16 + r;
#pragma unroll
        for (int j = 0; j < 4; ++j) {
            int a = a0 + wn + j * 8 + (lane & 3) * 2;
            int ua = a >> 1;
            cP_hi[(size_t)m * 256 + ua] = pack_h(acc[i][j][0], acc[i][j][1]);
            cP_hi[(size_t)(m + 8) * 256 + ua] = pack_h(acc[i][j][2], acc[i][j][3]);
        }
    }
}

// ================= fc2 (fp16 2-term) + residuals, transposed output ===========
__global__ void __launch_bounds__(256, 2) fc2_kernel(const float* __restrict__ bias,
                                                     const float* __restrict__ x,
                                                     float* __restrict__ out) {
    GEMM_PROLOG();
    int l0 = blockIdx.x * 128, c0 = blockIdx.y * 128, b = blockIdx.z;
    const int NC = 16;

    auto issue = [&](int c) {
        if (c < NC) {
            uint_t sb = dsm_u32 + (c & 3) * CS_STRIDE;
#pragma unroll
            for (int g = 0; g < 2; ++g) {
                int item = g * 256 + tid;
                int rw = item >> 2, gk = item & 3;
                uint_t d = SWZ(rw * 64 + gk * 16);
                size_t ao = (size_t)(c0 + rw) * 256 + c * 16 + gk * 4;
                cpa16(sb + d, w2_hi + ao, 1);
                cpa16(sb + 8192 + d, w2_lo + ao, 1);
                size_t bo = ((size_t)b * Lr + l0 + rw) * 256 + c * 16 + gk * 4;
                cpa16(sb + 16384 + d, cP_hi + bo, 1);
            }
        }
        CP_COMMIT();
    };

    PIPE4(NC, CS_STRIDE, mma_chunk32_h)

    int r = lane >> 2;
#pragma unroll
    for (int i = 0; i < 4; ++i) {
        int cc = c0 + wm + i * 16 + r;
        float b0 = bias[cc], b1 = bias[cc + 8];
#pragma unroll
        for (int j = 0; j < 4; ++j) {
            int l = l0 + wn + j * 8 + (lane & 3) * 2;
            size_t o0 = ((size_t)b * HALF + cc) * Lr + l;
            size_t o1 = ((size_t)b * HALF + cc + 8) * Lr + l;
            float2 h0 = *(const float2*)&g_h[o0];
            float2 x0 = *(const float2*)&x[o0];
            float2 h1 = *(const float2*)&g_h[o1];
            float2 x1 = *(const float2*)&x[o1];
            *(float2*)&out[o0] = make_float2(acc[i][j][0] + b0 + h0.x + x0.x,
                                             acc[i][j][1] + b0 + h0.y + x0.y);
            *(float2*)&out[o1] = make_float2(acc[i][j][2] + b1 + h1.x + x1.x,
                                             acc[i][j][3] + b1 + h1.y + x1.y);
        }
    }
}

// ================= launch =================
extern "C" void kernel_launch(void* const* d_in, const int* in_sizes, int n_in,
                              void* d_out, int out_size) {
    const float* x      = (const float*)d_in[0];
    const float* we     = (const float*)d_in[1];
    const float* img    = (const float*)d_in[2];
    const float* conv_v = (const float*)d_in[4];
    const float* conv_g = (const float*)d_in[5];
    const float* conv_b = (const float*)d_in[6];
    const float* fc1_w  = (const float*)d_in[7];
    const float* fc1_b  = (const float*)d_in[8];
    const float* fc2_w  = (const float*)d_in[9];
    const float* fc2_b  = (const float*)d_in[10];

    float* out = (float*)d_out;
    const size_t SZ_OUT = (size_t)Bn * HALF * Lr;
    const size_t SZ_WE  = (size_t)Bn * Lr * DW;
    const size_t SZ_IMG = (size_t)Bn * DW * HW;
    float* out_we   = out + SZ_OUT;
    float* out_img  = out_we + SZ_WE;
    float* out_attn = out_img + SZ_IMG;

    cudaFuncSetAttribute(conv_kernel, cudaFuncAttributeMaxDynamicSharedMemorySize, DSMEM_C);
    cudaFuncSetAttribute(fc1_kernel, cudaFuncAttributeMaxDynamicSharedMemorySize, DSMEM_G);
    cudaFuncSetAttribute(score_kernel, cudaFuncAttributeMaxDynamicSharedMemorySize, DSMEM_G);
    cudaFuncSetAttribute(ctx_kernel, cudaFuncAttributeMaxDynamicSharedMemorySize, DSMEM_C);
    cudaFuncSetAttribute(fc2_kernel, cudaFuncAttributeMaxDynamicSharedMemorySize, DSMEM_C);

    // prepass splits
    wsplit_fused_kernel<<<COUT, 256>>>(conv_v, conv_g);
    tsplit_xh_kernel<<<dim3(Lr / 32, CIN / 32, Bn), dim3(32, 8)>>>(x);
    ksplit_w1_kernel<<<DW, 256>>>(fc1_w);
    ksplit_w2_kernel<<<HALF, 256>>>(fc2_w);
    fTsplit_kernel<<<dim3(8, DW / 32, Bn), dim3(32, 8)>>>(img);
    fCsplit_kernel<<<dim3(DW, Bn), 128>>>(img);

    conv_kernel<<<dim3(Lr / 128, COUT / 128, Bn), 256, DSMEM_C>>>(conv_b);
    glu_tsplit_kernel<<<dim3(Lr / 32, HALF / 32, Bn), dim3(32, 8)>>>();
    fc1_kernel<<<dim3(DW / 128, (Bn * Lr) / 128), 256, DSMEM_G>>>(fc1_b, we);
    score_kernel<<<dim3(2, (Bn * Lr) / 128), 256, DSMEM_G>>>();
    softmax_kernel<<<(Bn * Lr) / 8, 256>>>(out_attn);
    ctx_kernel<<<dim3(DW / 128, (Bn * Lr) / 128), 256, DSMEM_C>>>();
    fc2_kernel<<<dim3(Lr / 128, HALF / 128, Bn), 256, DSMEM_C>>>(fc2_b, x, out);

    cudaMemcpyAsync(out_we, we, SZ_WE * sizeof(float), cudaMemcpyDeviceToDevice, 0);
    cudaMemcpyAsync(out_img, img, SZ_IMG * sizeof(float), cudaMemcpyDeviceToDevice, 0);
}

// round 17
// speedup vs baseline: 2.7965x; 1.0357x over previous
#include <cuda_runtime.h>
#include <math.h>

#define Bn   16
#define CIN  512
#define Lr   1024
#define COUT 1024
#define KW   5
#define DW   512
#define HW   196
#define HALF 512

typedef unsigned uint_t;

// ---- scratch (device globals; no allocation allowed) ----
__device__ float g_h[(size_t)Bn * HALF * Lr];      // GLU output (fp32, fc2 residual)
__device__ float g_score[(size_t)Bn * Lr * HW];

// conv planes: fp16 (2-term split, no B_lo plane)
__device__ __align__(16) uint_t wH_hi[COUT * 1280], wH_lo[COUT * 1280];          // A [co][k'=t*256+ci/2]
__device__ __align__(16) uint_t xH_hi[(size_t)Bn * Lr * 256];                    // B [b][l][ci/2]
// bf16 hi/lo planes (fc1 / score — precision-critical path)
__device__ __align__(16) uint_t hT_hi[(size_t)Bn * Lr * 256], hT_lo[(size_t)Bn * Lr * 256];   // fc1 A [b][l][c/2]
__device__ __align__(16) uint_t w1_hi[DW * 256], w1_lo[DW * 256];                // fc1 B [a][c/2]
__device__ __align__(16) uint_t qP_hi[(size_t)Bn * Lr * 256], qP_lo[(size_t)Bn * Lr * 256];   // score A [m][a/2]
__device__ __align__(16) uint_t fT_hi[(size_t)Bn * 256 * 256], fT_lo[(size_t)Bn * 256 * 256]; // score B [b][p pad256][dw/2]
// fp16 planes (ctx / fc2 — post-softmax path)
__device__ __align__(16) uint_t aP_hi[(size_t)Bn * Lr * 104], aP_lo[(size_t)Bn * Lr * 104];   // ctx A [m][p/2 pad104]
__device__ __align__(16) uint_t fC_hi[(size_t)Bn * DW * 104];                    // ctx B [b][a][p/2]
__device__ __align__(16) uint_t cP_hi[(size_t)Bn * Lr * 256];                    // fc2 B [m][a/2]
__device__ __align__(16) uint_t w2_hi[HALF * 256], w2_lo[HALF * 256];            // fc2 A [c][a/2]

// ---- split helpers ----
__device__ __forceinline__ void split2(float v0, float v1, uint_t& hi, uint_t& lo) {  // bf16
    asm("cvt.rn.bf16x2.f32 %0, %1, %2;" : "=r"(hi) : "f"(v1), "f"(v0));
    float h0 = __uint_as_float(hi << 16);
    float h1 = __uint_as_float(hi & 0xffff0000u);
    asm("cvt.rn.bf16x2.f32 %0, %1, %2;" : "=r"(lo) : "f"(v1 - h1), "f"(v0 - h0));
}
__device__ __forceinline__ void split2h(float v0, float v1, uint_t& hi, uint_t& lo) {  // fp16
    asm("cvt.rn.f16x2.f32 %0, %1, %2;" : "=r"(hi) : "f"(v1), "f"(v0));
    float h0, h1;
    asm("{\n\t.reg .b16 a,b;\n\tmov.b32 {a,b}, %2;\n\tcvt.f32.f16 %0, a;\n\tcvt.f32.f16 %1, b;\n\t}"
        : "=f"(h0), "=f"(h1) : "r"(hi));
    asm("cvt.rn.f16x2.f32 %0, %1, %2;" : "=r"(lo) : "f"(v1 - h1), "f"(v0 - h0));
}
__device__ __forceinline__ uint_t pack_h(float v0, float v1) {
    uint_t r;
    asm("cvt.rn.f16x2.f32 %0, %1, %2;" : "=r"(r) : "f"(v1), "f"(v0));
    return r;
}

__device__ __forceinline__ void mma_bf16(float* c, const uint_t* a, const uint_t* b) {
    asm volatile(
        "mma.sync.aligned.m16n8k16.row.col.f32.bf16.bf16.f32 "
        "{%0,%1,%2,%3}, {%4,%5,%6,%7}, {%8,%9}, {%0,%1,%2,%3};"
        : "+f"(c[0]), "+f"(c[1]), "+f"(c[2]), "+f"(c[3])
        : "r"(a[0]), "r"(a[1]), "r"(a[2]), "r"(a[3]), "r"(b[0]), "r"(b[1]));
}
__device__ __forceinline__ void mma_f16(float* c, const uint_t* a, const uint_t* b) {
    asm volatile(
        "mma.sync.aligned.m16n8k16.row.col.f32.f16.f16.f32 "
        "{%0,%1,%2,%3}, {%4,%5,%6,%7}, {%8,%9}, {%0,%1,%2,%3};"
        : "+f"(c[0]), "+f"(c[1]), "+f"(c[2]), "+f"(c[3])
        : "r"(a[0]), "r"(a[1]), "r"(a[2]), "r"(a[3]), "r"(b[0]), "r"(b[1]));
}

__device__ __forceinline__ void ldsm4r(uint_t* r, uint_t addr) {
    asm volatile("ldmatrix.sync.aligned.m8n8.x4.shared.b16 {%0,%1,%2,%3}, [%4];"
                 : "=r"(r[0]), "=r"(r[1]), "=r"(r[2]), "=r"(r[3]) : "r"(addr));
}

__device__ __forceinline__ void cpa16(uint_t sdst, const void* g, int ok) {
    asm volatile("cp.async.cg.shared.global [%0], [%1], 16, %2;"
                 :: "r"(sdst), "l"(g), "r"(ok ? 16 : 0) : "memory");
}
#define CP_COMMIT() asm volatile("cp.async.commit_group;" ::: "memory")

#define SWZ(o) ((o) ^ (((o) >> 3) & 0x70))

#define GS_STRIDE 32768
#define DSMEM_G  (3 * GS_STRIDE)
#define CS_STRIDE 24576
#define DSMEM_C  (4 * CS_STRIDE)  // 96KB; conv epilogue reuses it as float[128][129] (66KB)

#define ACC_INIT()                                    \
    float acc[4][4][4];                               \
    _Pragma("unroll") for (int i = 0; i < 4; ++i)     \
        _Pragma("unroll") for (int j = 0; j < 4; ++j) \
            _Pragma("unroll") for (int t = 0; t < 4; ++t) acc[i][j][t] = 0.f;

#define GEMM_PROLOG()                                            \
    extern __shared__ uint_t dsm[];                              \
    uint_t dsm_u32 = (uint_t)__cvta_generic_to_shared(dsm);      \
    int tid = threadIdx.x, lane = tid & 31, wid = tid >> 5;      \
    int wm = (wid & 1) * 64, wn = (wid >> 1) * 32;               \
    ACC_INIT();

// K=32 chunk, bf16 3-term
__device__ __forceinline__ void mma_chunk32(uint_t sb, int wm, int wn, int lane,
                                            float acc[4][4][4]) {
    int l7 = lane & 7;
    int arow = ((lane >> 3) & 1) * 8 + l7;
    int aslot = lane >> 4;
    int brow = (lane >> 4) * 8 + l7;
    int bslot = (lane >> 3) & 1;
#pragma unroll
    for (int h = 0; h < 2; ++h) {
        uint_t ah[4][4], bh[4][2];
#pragma unroll
        for (int i = 0; i < 4; ++i)
            ldsm4r(ah[i], sb + SWZ((wm + i * 16 + arow) * 64 + h * 32 + aslot * 16));
#pragma unroll
        for (int jp = 0; jp < 2; ++jp) {
            uint_t r[4];
            ldsm4r(r, sb + 16384 + SWZ((wn + jp * 16 + brow) * 64 + h * 32 + bslot * 16));
            bh[2 * jp][0] = r[0]; bh[2 * jp][1] = r[1];
            bh[2 * jp + 1][0] = r[2]; bh[2 * jp + 1][1] = r[3];
        }
#pragma unroll
        for (int i = 0; i < 4; ++i)
#pragma unroll
            for (int j = 0; j < 4; ++j) mma_bf16(acc[i][j], ah[i], bh[j]);
        {
            uint_t bl[4][2];
#pragma unroll
            for (int jp = 0; jp < 2; ++jp) {
                uint_t r[4];
                ldsm4r(r, sb + 24576 + SWZ((wn + jp * 16 + brow) * 64 + h * 32 + bslot * 16));
                bl[2 * jp][0] = r[0]; bl[2 * jp][1] = r[1];
                bl[2 * jp + 1][0] = r[2]; bl[2 * jp + 1][1] = r[3];
            }
#pragma unroll
            for (int i = 0; i < 4; ++i)
#pragma unroll
                for (int j = 0; j < 4; ++j) mma_bf16(acc[i][j], ah[i], bl[j]);
        }
        {
            uint_t al[4][4];
#pragma unroll
            for (int i = 0; i < 4; ++i)
                ldsm4r(al[i], sb + 8192 + SWZ((wm + i * 16 + arow) * 64 + h * 32 + aslot * 16));
#pragma unroll
            for (int i = 0; i < 4; ++i)
#pragma unroll
                for (int j = 0; j < 4; ++j) mma_bf16(acc[i][j], al[i], bh[j]);
        }
    }
}

// K=32 chunk, fp16 2-term
__device__ __forceinline__ void mma_chunk32_h(uint_t sb, int wm, int wn, int lane,
                                              float acc[4][4][4]) {
    int l7 = lane & 7;
    int arow = ((lane >> 3) & 1) * 8 + l7;
    int aslot = lane >> 4;
    int brow = (lane >> 4) * 8 + l7;
    int bslot = (lane >> 3) & 1;
#pragma unroll
    for (int h = 0; h < 2; ++h) {
        uint_t ah[4][4], bh[4][2];
#pragma unroll
        for (int i = 0; i < 4; ++i)
            ldsm4r(ah[i], sb + SWZ((wm + i * 16 + arow) * 64 + h * 32 + aslot * 16));
#pragma unroll
        for (int jp = 0; jp < 2; ++jp) {
            uint_t r[4];
            ldsm4r(r, sb + 16384 + SWZ((wn + jp * 16 + brow) * 64 + h * 32 + bslot * 16));
            bh[2 * jp][0] = r[0]; bh[2 * jp][1] = r[1];
            bh[2 * jp + 1][0] = r[2]; bh[2 * jp + 1][1] = r[3];
        }
#pragma unroll
        for (int i = 0; i < 4; ++i)
#pragma unroll
            for (int j = 0; j < 4; ++j) mma_f16(acc[i][j], ah[i], bh[j]);
        {
            uint_t al[4][4];
#pragma unroll
            for (int i = 0; i < 4; ++i)
                ldsm4r(al[i], sb + 8192 + SWZ((wm + i * 16 + arow) * 64 + h * 32 + aslot * 16));
#pragma unroll
            for (int i = 0; i < 4; ++i)
#pragma unroll
                for (int j = 0; j < 4; ++j) mma_f16(acc[i][j], al[i], bh[j]);
        }
    }
}

#define PIPE3(NC, STRIDE, CHUNK)                                   \
    issue(0);                                                      \
    for (int c = 0; c < (NC); ++c) {                               \
        issue(c + 1);                                              \
        asm volatile("cp.async.wait_group 1;" ::: "memory");       \
        __syncthreads();                                           \
        CHUNK(dsm_u32 + (c % 3) * (STRIDE), wm, wn, lane, acc);    \
    }

#define PIPE4(NC, STRIDE, CHUNK)                                   \
    issue(0); issue(1);                                            \
    for (int c = 0; c < (NC); ++c) {                               \
        issue(c + 2);                                              \
        asm volatile("cp.async.wait_group 2;" ::: "memory");       \
        __syncthreads();                                           \
        CHUNK(dsm_u32 + (c & 3) * (STRIDE), wm, wn, lane, acc);    \
    }

// ================= prepass kernels =================
__global__ void wsplit_fused_kernel(const float* __restrict__ v, const float* __restrict__ g) {
    __shared__ float vbuf[CIN * KW];
    __shared__ float red[256];
    int co = blockIdx.x, tid = threadIdx.x;
    const float* vp = v + (size_t)co * (CIN * KW);
    float s = 0.f;
    for (int i = tid; i < CIN * KW; i += 256) {
        float t = vp[i];
        vbuf[i] = t;
        s += t * t;
    }
    red[tid] = s;
    __syncthreads();
    for (int o = 128; o > 0; o >>= 1) {
        if (tid < o) red[tid] += red[tid + o];
        __syncthreads();
    }
    float sc = g[co] * rsqrtf(red[0]);
    for (int kp = tid; kp < 1280; kp += 256) {
        int t = kp >> 8, ci = (kp & 255) * 2;
        int si = ci * KW + t;
        uint_t hi, lo;
        split2h(vbuf[si] * sc, vbuf[si + KW] * sc, hi, lo);
        wH_hi[(size_t)co * 1280 + kp] = hi;
        wH_lo[(size_t)co * 1280 + kp] = lo;
    }
}

__global__ void tsplit_xh_kernel(const float* __restrict__ x) {
    __shared__ float tile[32][33];
    int l0 = blockIdx.x * 32, c0 = blockIdx.y * 32, b = blockIdx.z;
    int tx = threadIdx.x, ty0 = threadIdx.y;
#pragma unroll
    for (int i = 0; i < 32; i += 8)
        tile[ty0 + i][tx] = x[((size_t)b * CIN + c0 + ty0 + i) * Lr + l0 + tx];
    __syncthreads();
    int id = ty0 * 32 + tx;
#pragma unroll
    for (int rpt = 0; rpt < 2; ++rpt) {
        int item = id + 256 * rpt;
        int l = item >> 4, u = item & 15;
        xH_hi[((size_t)b * Lr + l0 + l) * 256 + c0 / 2 + u] =
            pack_h(tile[2 * u][l], tile[2 * u + 1][l]);
    }
}

// merged w1 (bf16) + w2 (fp16) split
__global__ void ksplit_w12_kernel(const float* __restrict__ w1, const float* __restrict__ w2) {
    int n = blockIdx.x, kp = threadIdx.x;
    if (n < DW) {
        float2 p = *(const float2*)&w1[(size_t)n * DW + 2 * kp];
        uint_t hi, lo;
        split2(p.x, p.y, hi, lo);
        w1_hi[(size_t)n * 256 + kp] = hi;
        w1_lo[(size_t)n * 256 + kp] = lo;
    } else {
        int n2 = n - DW;
        float2 p = *(const float2*)&w2[(size_t)n2 * DW + 2 * kp];
        uint_t hi, lo;
        split2h(p.x, p.y, hi, lo);
        w2_hi[(size_t)n2 * 256 + kp] = hi;
        w2_lo[(size_t)n2 * 256 + kp] = lo;
    }
}

__global__ void fTsplit_kernel(const float* __restrict__ img) {
    __shared__ float tile[32][33];
    int p0 = blockIdx.x * 32, d0 = blockIdx.y * 32, b = blockIdx.z;
    int tx = threadIdx.x, ty0 = threadIdx.y;
#pragma unroll
    for (int i = 0; i < 32; i += 8) {
        int p = p0 + tx;
        tile[ty0 + i][tx] = (p < HW) ? img[((size_t)b * DW + d0 + ty0 + i) * HW + p] : 0.f;
    }
    __syncthreads();
    int id = ty0 * 32 + tx;
#pragma unroll
    for (int rpt = 0; rpt < 2; ++rpt) {
        int item = id + 256 * rpt;
        int p = item >> 4, u = item & 15;
        uint_t hi, lo;
        split2(tile[2 * u][p], tile[2 * u + 1][p], hi, lo);
        size_t o = ((size_t)b * 256 + p0 + p) * 256 + d0 / 2 + u;
        fT_hi[o] = hi;
        fT_lo[o] = lo;
    }
}

__global__ void fCsplit_kernel(const float* __restrict__ img) {
    int a = blockIdx.x, b = blockIdx.y, kp = threadIdx.x;
    if (kp >= 104) return;
    int p = 2 * kp;
    float v0 = (p < HW) ? img[((size_t)b * DW + a) * HW + p] : 0.f;
    float v1 = (p + 1 < HW) ? img[((size_t)b * DW + a) * HW + p + 1] : 0.f;
    fC_hi[((size_t)b * DW + a) * 104 + kp] = pack_h(v0, v1);
}

// ===== conv (fp16 2-term) with paired-channel M tile + fused GLU epilogue =====
// M rows 0..63  -> a channels  jy*64 + rw
// M rows 64..127-> gate chans  512 + jy*64 + (rw-64)
__global__ void __launch_bounds__(256, 2) conv_kernel(const float* __restrict__ bias) {
    GEMM_PROLOG();
    int l0 = blockIdx.x * 128, jy = blockIdx.y, bz = blockIdx.z;
    int c64 = jy * 64;
    const int NC = 80;  // 5 taps * 16 k32-chunks

    auto issue = [&](int c) {
        if (c < NC) {
            uint_t sb = dsm_u32 + (c & 3) * CS_STRIDE;
            int t = c >> 4;
#pragma unroll
            for (int g = 0; g < 2; ++g) {
                int item = g * 256 + tid;
                int rw = item >> 2, gk = item & 3;
                int co = c64 + (rw & 63) + ((rw >> 6) << 9);
                uint_t d = SWZ(rw * 64 + gk * 16);
                size_t ao = (size_t)co * 1280 + c * 16 + gk * 4;
                cpa16(sb + d, wH_hi + ao, 1);
                cpa16(sb + 8192 + d, wH_lo + ao, 1);
                int xr = l0 + rw + t - 4;
                int ok = xr >= 0;
                size_t bo = ((size_t)bz * Lr + (ok ? xr : 0)) * 256 + (c & 15) * 16 + gk * 4;
                cpa16(sb + 16384 + d, xH_hi + bo, ok);
            }
        }
        CP_COMMIT();
    };

    PIPE4(NC, CS_STRIDE, mma_chunk32_h)

    // ---- fused epilogue: bias -> smem tile -> GLU -> g_h + hT planes ----
    __syncthreads();  // all warps done with pipeline smem
    float* tile = (float*)dsm;  // [128][129]
    int r = lane >> 2;
#pragma unroll
    for (int i = 0; i < 4; ++i) {
        int rw0 = wm + i * 16 + r;
        float b0 = bias[c64 + (rw0 & 63) + ((rw0 >> 6) << 9)];
        float b1 = bias[c64 + ((rw0 + 8) & 63) + (((rw0 + 8) >> 6) << 9)];
#pragma unroll
        for (int j = 0; j < 4; ++j) {
            int l = wn + j * 8 + (lane & 3) * 2;
            tile[rw0 * 129 + l] = acc[i][j][0] + b0;
            tile[rw0 * 129 + l + 1] = acc[i][j][1] + b0;
            tile[(rw0 + 8) * 129 + l] = acc[i][j][2] + b1;
            tile[(rw0 + 8) * 129 + l + 1] = acc[i][j][3] + b1;
        }
    }
    __syncthreads();
    // phase 2a: h = a * sigmoid(gate); write g_h, store h back into a-half
#pragma unroll
    for (int it = 0; it < 32; ++it) {
        int idx = it * 256 + tid;
        int ch = idx >> 7, l = idx & 127;
        float a = tile[ch * 129 + l];
        float gv = tile[(ch + 64) * 129 + l];
        float h = a * (1.f / (1.f + expf(-gv)));
        tile[ch * 129 + l] = h;
        g_h[((size_t)bz * HALF + c64 + ch) * Lr + l0 + l] = h;
    }
    __syncthreads();
    // phase 2b: transpose-split -> hT planes (bf16)
#pragma unroll
    for (int it = 0; it < 16; ++it) {
        int idx = it * 256 + tid;
        int l = idx >> 5, u = idx & 31;
        uint_t hi, lo;
        split2(tile[(2 * u) * 129 + l], tile[(2 * u + 1) * 129 + l], hi, lo);
        size_t o = ((size_t)bz * Lr + l0 + l) * 256 + jy * 32 + u;
        hT_hi[o] = hi;
        hT_lo[o] = lo;
    }
}

// ================= fc1: q = h^T W1^T + b1 + we -> q planes (bf16x3) ===========
__global__ void __launch_bounds__(256, 2) fc1_kernel(const float* __restrict__ bias,
                                                     const float* __restrict__ we) {
    GEMM_PROLOG();
    int a0 = blockIdx.x * 128, m0 = blockIdx.y * 128;
    int b = m0 >> 10, l0 = m0 & 1023;
    const int NC = 16;

    auto issue = [&](int c) {
        if (c < NC) {
            uint_t sb = dsm_u32 + (c % 3) * GS_STRIDE;
#pragma unroll
            for (int g = 0; g < 2; ++g) {
                int item = g * 256 + tid;
                int rw = item >> 2, gk = item & 3;
                uint_t d = SWZ(rw * 64 + gk * 16);
                size_t ao = ((size_t)b * Lr + l0 + rw) * 256 + c * 16 + gk * 4;
                cpa16(sb + d, hT_hi + ao, 1);
                cpa16(sb + 8192 + d, hT_lo + ao, 1);
                size_t bo = (size_t)(a0 + rw) * 256 + c * 16 + gk * 4;
                cpa16(sb + 16384 + d, w1_hi + bo, 1);
                cpa16(sb + 24576 + d, w1_lo + bo, 1);
            }
        }
        CP_COMMIT();
    };

    PIPE3(NC, GS_STRIDE, mma_chunk32)

    int r = lane >> 2;
#pragma unroll
    for (int i = 0; i < 4; ++i) {
        int m = m0 + wm + i * 16 + r;
#pragma unroll
        for (int j = 0; j < 4; ++j) {
            int a = a0 + wn + j * 8 + (lane & 3) * 2;
            int ua = a >> 1;
            float2 bb = *(const float2*)&bias[a];
            float2 w0 = *(const float2*)&we[(size_t)m * DW + a];
            float2 w1v = *(const float2*)&we[(size_t)(m + 8) * DW + a];
            uint_t hi, lo;
            split2(acc[i][j][0] + bb.x + w0.x, acc[i][j][1] + bb.y + w0.y, hi, lo);
            qP_hi[(size_t)m * 256 + ua] = hi;
            qP_lo[(size_t)m * 256 + ua] = lo;
            split2(acc[i][j][2] + bb.x + w1v.x, acc[i][j][3] + bb.y + w1v.y, hi, lo);
            qP_hi[(size_t)(m + 8) * 256 + ua] = hi;
            qP_lo[(size_t)(m + 8) * 256 + ua] = lo;
        }
    }
}

// ================= score = q @ feat (bf16x3) =================
__global__ void __launch_bounds__(256, 2) score_kernel() {
    GEMM_PROLOG();
    int p0 = blockIdx.x * 128, m0 = blockIdx.y * 128;
    int b = m0 >> 10;
    const int NC = 16;

    auto issue = [&](int c) {
        if (c < NC) {
            uint_t sb = dsm_u32 + (c % 3) * GS_STRIDE;
#pragma unroll
            for (int g = 0; g < 2; ++g) {
                int item = g * 256 + tid;
                int rw = item >> 2, gk = item & 3;
                uint_t d = SWZ(rw * 64 + gk * 16);
                size_t ao = (size_t)(m0 + rw) * 256 + c * 16 + gk * 4;
                cpa16(sb + d, qP_hi + ao, 1);
                cpa16(sb + 8192 + d, qP_lo + ao, 1);
                size_t bo = ((size_t)b * 256 + p0 + rw) * 256 + c * 16 + gk * 4;
                cpa16(sb + 16384 + d, fT_hi + bo, 1);
                cpa16(sb + 24576 + d, fT_lo + bo, 1);
            }
        }
        CP_COMMIT();
    };

    PIPE3(NC, GS_STRIDE, mma_chunk32)

    int r = lane >> 2;
#pragma unroll
    for (int i = 0; i < 4; ++i) {
        int m = m0 + wm + i * 16 + r;
#pragma unroll
        for (int j = 0; j < 4; ++j) {
            int p = p0 + wn + j * 8 + (lane & 3) * 2;
            if (p < HW) {
                *(float2*)&g_score[(size_t)m * HW + p] =
                    make_float2(acc[i][j][0], acc[i][j][1]);
                *(float2*)&g_score[(size_t)(m + 8) * HW + p] =
                    make_float2(acc[i][j][2], acc[i][j][3]);
            }
        }
    }
}

// ================= softmax over 196 (+ fused fp16 aP split) =================
__global__ void softmax_kernel(float* __restrict__ attn) {
    __shared__ float sv[8][200];
    int warp = (blockIdx.x * blockDim.x + threadIdx.x) >> 5;
    int wloc = (threadIdx.x >> 5);
    int lane = threadIdx.x & 31;
    if (warp >= Bn * Lr) return;
    const float* sp = g_score + (size_t)warp * HW;
    float v[7];
    float mx = -1e30f;
#pragma unroll
    for (int i = 0; i < 7; ++i) {
        int p = lane + 32 * i;
        v[i] = (p < HW) ? sp[p] : -1e30f;
        mx = fmaxf(mx, v[i]);
    }
#pragma unroll
    for (int o = 16; o > 0; o >>= 1) mx = fmaxf(mx, __shfl_xor_sync(0xffffffffu, mx, o));
    float sum = 0.f;
#pragma unroll
    for (int i = 0; i < 7; ++i) {
        int p = lane + 32 * i;
        v[i] = (p < HW) ? expf(v[i] - mx) : 0.f;
        sum += v[i];
    }
#pragma unroll
    for (int o = 16; o > 0; o >>= 1) sum += __shfl_xor_sync(0xffffffffu, sum, o);
    float inv = 1.f / sum;
#pragma unroll
    for (int i = 0; i < 7; ++i) {
        int p = lane + 32 * i;
        if (p < HW) {
            float r = v[i] * inv;
            attn[(size_t)warp * HW + p] = r;
            sv[wloc][p] = r;
        }
    }
    __syncwarp();
#pragma unroll
    for (int kq = 0; kq < 4; ++kq) {
        int kp = lane + 32 * kq;
        if (kp < 104) {
            int p = 2 * kp;
            float v0 = (p < HW) ? sv[wloc][p] : 0.f;
            float v1 = (p + 1 < HW) ? sv[wloc][p + 1] : 0.f;
            uint_t hi, lo;
            split2h(v0, v1, hi, lo);
            aP_hi[(size_t)warp * 104 + kp] = hi;
            aP_lo[(size_t)warp * 104 + kp] = lo;
        }
    }
}

// ================= ctx = attn @ feat^T (fp16 2-term) -> cP hi plane ===========
__global__ void __launch_bounds__(256, 2) ctx_kernel() {
    GEMM_PROLOG();
    int a0 = blockIdx.x * 128, m0 = blockIdx.y * 128;
    int b = m0 >> 10;
    const int NC = 7;

    auto issue = [&](int c) {
        if (c < NC) {
            uint_t sb = dsm_u32 + (c & 3) * CS_STRIDE;
#pragma unroll
            for (int g = 0; g < 2; ++g) {
                int item = g * 256 + tid;
                int rw = item >> 2, gk = item & 3;
                uint_t d = SWZ(rw * 64 + gk * 16);
                int kp = c * 16 + gk * 4;
                int ok = kp < 104;
                size_t ao = (size_t)(m0 + rw) * 104 + kp;
                cpa16(sb + d, aP_hi + (ok ? ao : 0), ok);
                cpa16(sb + 8192 + d, aP_lo + (ok ? ao : 0), ok);
                size_t bo = ((size_t)b * DW + a0 + rw) * 104 + kp;
                cpa16(sb + 16384 + d, fC_hi + (ok ? bo : 0), ok);
            }
        }
        CP_COMMIT();
    };

    PIPE4(NC, CS_STRIDE, mma_chunk32_h)

    int r = lane >> 2;
#pragma unroll
    for (int i = 0; i < 4; ++i) {
        int m = m0 + wm + i * 16 + r;
#pragma unroll
        for (int j = 0; j < 4; ++j) {
            int a = a0 + wn + j * 8 + (lane & 3) * 2;
            int ua = a >> 1;
            cP_hi[(size_t)m * 256 + ua] = pack_h(acc[i][j][0], acc[i][j][1]);
            cP_hi[(size_t)(m + 8) * 256 + ua] = pack_h(acc[i][j][2], acc[i][j][3]);
        }
    }
}

// ================= fc2 (fp16 2-term) + residuals, transposed output ===========
__global__ void __launch_bounds__(256, 2) fc2_kernel(const float* __restrict__ bias,
                                                     const float* __restrict__ x,
                                                     float* __restrict__ out) {
    GEMM_PROLOG();
    int l0 = blockIdx.x * 128, c0 = blockIdx.y * 128, b = blockIdx.z;
    const int NC = 16;

    auto issue = [&](int c) {
        if (c < NC) {
            uint_t sb = dsm_u32 + (c & 3) * CS_STRIDE;
#pragma unroll
            for (int g = 0; g < 2; ++g) {
                int item = g * 256 + tid;
                int rw = item >> 2, gk = item & 3;
                uint_t d = SWZ(rw * 64 + gk * 16);
                size_t ao = (size_t)(c0 + rw) * 256 + c * 16 + gk * 4;
                cpa16(sb + d, w2_hi + ao, 1);
                cpa16(sb + 8192 + d, w2_lo + ao, 1);
                size_t bo = ((size_t)b * Lr + l0 + rw) * 256 + c * 16 + gk * 4;
                cpa16(sb + 16384 + d, cP_hi + bo, 1);
            }
        }
        CP_COMMIT();
    };

    PIPE4(NC, CS_STRIDE, mma_chunk32_h)

    int r = lane >> 2;
#pragma unroll
    for (int i = 0; i < 4; ++i) {
        int cc = c0 + wm + i * 16 + r;
        float b0 = bias[cc], b1 = bias[cc + 8];
#pragma unroll
        for (int j = 0; j < 4; ++j) {
            int l = l0 + wn + j * 8 + (lane & 3) * 2;
            size_t o0 = ((size_t)b * HALF + cc) * Lr + l;
            size_t o1 = ((size_t)b * HALF + cc + 8) * Lr + l;
            float2 h0 = *(const float2*)&g_h[o0];
            float2 x0 = *(const float2*)&x[o0];
            float2 h1 = *(const float2*)&g_h[o1];
            float2 x1 = *(const float2*)&x[o1];
            *(float2*)&out[o0] = make_float2(acc[i][j][0] + b0 + h0.x + x0.x,
                                             acc[i][j][1] + b0 + h0.y + x0.y);
            *(float2*)&out[o1] = make_float2(acc[i][j][2] + b1 + h1.x + x1.x,
                                             acc[i][j][3] + b1 + h1.y + x1.y);
        }
    }
}

// ================= launch =================
extern "C" void kernel_launch(void* const* d_in, const int* in_sizes, int n_in,
                              void* d_out, int out_size) {
    const float* x      = (const float*)d_in[0];
    const float* we     = (const float*)d_in[1];
    const float* img    = (const float*)d_in[2];
    const float* conv_v = (const float*)d_in[4];
    const float* conv_g = (const float*)d_in[5];
    const float* conv_b = (const float*)d_in[6];
    const float* fc1_w  = (const float*)d_in[7];
    const float* fc1_b  = (const float*)d_in[8];
    const float* fc2_w  = (const float*)d_in[9];
    const float* fc2_b  = (const float*)d_in[10];

    float* out = (float*)d_out;
    const size_t SZ_OUT = (size_t)Bn * HALF * Lr;
    const size_t SZ_WE  = (size_t)Bn * Lr * DW;
    const size_t SZ_IMG = (size_t)Bn * DW * HW;
    float* out_we   = out + SZ_OUT;
    float* out_img  = out_we + SZ_WE;
    float* out_attn = out_img + SZ_IMG;

    cudaFuncSetAttribute(conv_kernel, cudaFuncAttributeMaxDynamicSharedMemorySize, DSMEM_C);
    cudaFuncSetAttribute(fc1_kernel, cudaFuncAttributeMaxDynamicSharedMemorySize, DSMEM_G);
    cudaFuncSetAttribute(score_kernel, cudaFuncAttributeMaxDynamicSharedMemorySize, DSMEM_G);
    cudaFuncSetAttribute(ctx_kernel, cudaFuncAttributeMaxDynamicSharedMemorySize, DSMEM_C);
    cudaFuncSetAttribute(fc2_kernel, cudaFuncAttributeMaxDynamicSharedMemorySize, DSMEM_C);

    // prepass splits
    wsplit_fused_kernel<<<COUT, 256>>>(conv_v, conv_g);
    tsplit_xh_kernel<<<dim3(Lr / 32, CIN / 32, Bn), dim3(32, 8)>>>(x);
    ksplit_w12_kernel<<<DW + HALF, 256>>>(fc1_w, fc2_w);
    fTsplit_kernel<<<dim3(8, DW / 32, Bn), dim3(32, 8)>>>(img);
    fCsplit_kernel<<<dim3(DW, Bn), 128>>>(img);

    conv_kernel<<<dim3(Lr / 128, HALF / 64, Bn), 256, DSMEM_C>>>(conv_b);
    fc1_kernel<<<dim3(DW / 128, (Bn * Lr) / 128), 256, DSMEM_G>>>(fc1_b, we);
    score_kernel<<<dim3(2, (Bn * Lr) / 128), 256, DSMEM_G>>>();
    softmax_kernel<<<(Bn * Lr) / 8, 256>>>(out_attn);
    ctx_kernel<<<dim3(DW / 128, (Bn * Lr) / 128), 256, DSMEM_C>>>();
    fc2_kernel<<<dim3(Lr / 128, HALF / 128, Bn), 256, DSMEM_C>>>(fc2_b, x, out);

    cudaMemcpyAsync(out_we, we, SZ_WE * sizeof(float), cudaMemcpyDeviceToDevice, 0);
    cudaMemcpyAsync(out_img, img, SZ_IMG * sizeof(float), cudaMemcpyDeviceToDevice, 0);
}